// round 1
// baseline (speedup 1.0000x reference)
#include <cuda_runtime.h>
#include <cuda_bf16.h>
#include <math.h>

// ---------------------------------------------------------------------------
// Scratch (__device__ globals; no runtime allocation allowed)
// ---------------------------------------------------------------------------
__device__ float g_om1 [16*147*128*128];   // stage1 offset-conv output
__device__ float g_col1[16*147*128*128];   // stage1 sampled im2col (Cin*K = 3*49)
__device__ float g_t1  [16*64*128*128];    // stage1 main conv out / h1 (IN in-place)
__device__ float g_om2 [16*48*64*64];
__device__ float g_col2[16*1024*64*64];    // 64*16
__device__ float g_t2  [16*128*64*64];
__device__ float g_om3 [16*48*32*32];
__device__ float g_col3[16*2048*32*32];    // 128*16
__device__ float g_t3  [16*256*32*32];
__device__ float g_pad [16*256*34*34];     // reflect-padded res-block input
__device__ float g_y   [16*256*32*32];
__device__ float g_cv  [16*256*32*32];
__device__ float g_h   [16*256*32*32];

// ---------------------------------------------------------------------------
// Generic conv-as-GEMM with on-the-fly im2col (zero padding).
// out[b,m,oy,ox] = bias[m] + sum_{ci,ky,kx} W[m, ci*KH*KW + ky*KW+kx] *
//                  in[b,ci, oy*STR-PAD+ky, ox*STR-PAD+kx]
// 1x1/stride1/pad0 instantiations degenerate to a pure GEMM on a [B,CIN,H,W]
// "col" tensor. All shape params are template constants -> cheap indexing.
// ---------------------------------------------------------------------------
template<int CIN,int H,int W,int KH,int KW,int STR,int PAD,int HO,int WO>
__global__ void __launch_bounds__(256)
conv_gemm_kernel(const float* __restrict__ in, const float* __restrict__ Wt,
                 const float* __restrict__ bias, float* __restrict__ out, int M)
{
    constexpr int B    = 16;
    constexpr int Kdim = CIN*KH*KW;
    constexpr int HW   = HO*WO;
    constexpr int Ntot = B*HW;
    constexpr int BM = 64, BN = 64, BK = 16;

    __shared__ float As[BK][BM+4];   // +4 keeps 16B alignment, reduces conflicts
    __shared__ float Bs[BK][BN];

    const int t     = threadIdx.x;          // 256 threads
    const int nTile = blockIdx.x * BN;
    const int mTile = blockIdx.y * BM;

    // B-load mapping: element (k0+kl0+i*4, nTile + nl)
    const int nl  = t & 63;
    const int kl0 = t >> 6;                 // 0..3
    const int n   = nTile + nl;
    const bool nvalid = (n < Ntot);
    const int b   = n / HW;
    const int rem = n % HW;
    const int oy  = rem / WO;
    const int ox  = rem % WO;
    const int iy0 = oy*STR - PAD;
    const int ix0 = ox*STR - PAD;

    // A-load mapping: element (k0+kA, mTile + mA0 + i*16)
    const int kA  = t & 15;
    const int mA0 = t >> 4;

    const int tIdm = t >> 4;                // 0..15 -> m micro-tile
    const int tIdn = t & 15;                // 0..15 -> n micro-tile

    float acc[4][4] = {};

    for (int k0 = 0; k0 < Kdim; k0 += BK) {
        // ---- load A tile (weights) ----
        #pragma unroll
        for (int i = 0; i < 4; i++) {
            const int m = mTile + mA0 + i*16;
            const int k = k0 + kA;
            float v = 0.f;
            if (m < M && k < Kdim) v = Wt[m*Kdim + k];
            As[kA][mA0 + i*16] = v;
        }
        // ---- load B tile (im2col on the fly) ----
        #pragma unroll
        for (int i = 0; i < 4; i++) {
            const int k = k0 + kl0 + i*4;
            float v = 0.f;
            if (nvalid && k < Kdim) {
                const int ci = k / (KH*KW);
                const int r  = k % (KH*KW);
                const int ky = r / KW;
                const int kx = r % KW;
                const int iy = iy0 + ky;
                const int ix = ix0 + kx;
                if (iy >= 0 && iy < H && ix >= 0 && ix < W)
                    v = in[((b*CIN + ci)*H + iy)*W + ix];
            }
            Bs[kl0 + i*4][nl] = v;
        }
        __syncthreads();

        #pragma unroll
        for (int kk = 0; kk < BK; kk++) {
            float a[4], bb[4];
            #pragma unroll
            for (int i = 0; i < 4; i++) a[i]  = As[kk][tIdm*4 + i];
            #pragma unroll
            for (int j = 0; j < 4; j++) bb[j] = Bs[kk][tIdn*4 + j];
            #pragma unroll
            for (int i = 0; i < 4; i++)
                #pragma unroll
                for (int j = 0; j < 4; j++)
                    acc[i][j] += a[i] * bb[j];
        }
        __syncthreads();
    }

    // ---- store ----
    #pragma unroll
    for (int i = 0; i < 4; i++) {
        const int m = mTile + tIdm*4 + i;
        if (m >= M) continue;
        const float bv = bias ? bias[m] : 0.f;
        #pragma unroll
        for (int j = 0; j < 4; j++) {
            const int nn = nTile + tIdn*4 + j;
            if (nn < Ntot) {
                const int b2 = nn / HW;
                const int r2 = nn % HW;
                out[((size_t)b2*M + m)*HW + r2] = acc[i][j] + bv;
            }
        }
    }
}

// ---------------------------------------------------------------------------
// DCNv2 sampling: col[b, ci*K + k, oy, ox] = mask * bilinear(x[b,ci], ys, xs)
// om layout: off_y = ch 2k, off_x = ch 2k+1, mask = sigmoid(ch 2K+k)
// ---------------------------------------------------------------------------
template<int CIN,int H,int W,int KH,int KW,int STR,int PAD,int HO,int WO>
__global__ void __launch_bounds__(256)
deform_sample_kernel(const float* __restrict__ x, const float* __restrict__ om,
                     float* __restrict__ col)
{
    constexpr int B  = 16;
    constexpr int K  = KH*KW;
    constexpr int HW = HO*WO;

    const int idx = blockIdx.x*blockDim.x + threadIdx.x;  // over B*K*HO*WO
    if (idx >= B*K*HW) return;

    const int ox  = idx % WO;
    int tmp       = idx / WO;
    const int oy  = tmp % HO;  tmp /= HO;
    const int k   = tmp % K;
    const int b   = tmp / K;
    const int ky  = k / KW;
    const int kx  = k % KW;

    const int pix = oy*WO + ox;
    const float offy = om[((b*3*K + 2*k    )*HW) + pix];
    const float offx = om[((b*3*K + 2*k + 1)*HW) + pix];
    const float mv   = om[((b*3*K + 2*K + k)*HW) + pix];
    const float mask = 1.f / (1.f + expf(-mv));

    const float ys = (float)(oy*STR - PAD + ky) + offy;
    const float xs = (float)(ox*STR - PAD + kx) + offx;

    const float y0f = floorf(ys), x0f = floorf(xs);
    const float dy = ys - y0f,    dx = xs - x0f;
    const int y0 = (int)y0f, x0 = (int)x0f;
    const int y1 = y0 + 1,   x1 = x0 + 1;

    const bool vy0 = (y0 >= 0) & (y0 < H);
    const bool vy1 = (y1 >= 0) & (y1 < H);
    const bool vx0 = (x0 >= 0) & (x0 < W);
    const bool vx1 = (x1 >= 0) & (x1 < W);

    const int cy0 = min(max(y0, 0), H-1), cy1 = min(max(y1, 0), H-1);
    const int cx0 = min(max(x0, 0), W-1), cx1 = min(max(x1, 0), W-1);

    const float f00 = (vy0 && vx0) ? (1.f-dy)*(1.f-dx)*mask : 0.f;
    const float f01 = (vy0 && vx1) ? (1.f-dy)*dx*mask       : 0.f;
    const float f10 = (vy1 && vx0) ? dy*(1.f-dx)*mask       : 0.f;
    const float f11 = (vy1 && vx1) ? dy*dx*mask             : 0.f;

    const int i00 = cy0*W + cx0, i01 = cy0*W + cx1;
    const int i10 = cy1*W + cx0, i11 = cy1*W + cx1;

    const float* xb = x + (size_t)b*CIN*H*W;
    float* cp = col + (((size_t)b*CIN*K + k)*HW) + pix;

    #pragma unroll 4
    for (int ci = 0; ci < CIN; ci++) {
        const float* img = xb + (size_t)ci*H*W;
        const float v = f00*img[i00] + f01*img[i01] + f10*img[i10] + f11*img[i11];
        cp[(size_t)ci*K*HW] = v;
    }
}

// ---------------------------------------------------------------------------
// Instance norm (two-pass, per (b,c) block) + optional ReLU + optional add.
// In-place safe (reads complete before the element is rewritten).
// ---------------------------------------------------------------------------
__global__ void __launch_bounds__(256)
instnorm_kernel(const float* __restrict__ in, float* __restrict__ out,
                const float* __restrict__ addsrc, int HW, int relu)
{
    const int bc = blockIdx.x;
    const float* p = in + (size_t)bc*HW;
    float* q = out + (size_t)bc*HW;
    const float* a = addsrc ? addsrc + (size_t)bc*HW : nullptr;

    __shared__ float red[256];
    __shared__ float s_mu, s_rs;
    const int t = threadIdx.x;

    float s = 0.f;
    for (int i = t; i < HW; i += 256) s += p[i];
    red[t] = s; __syncthreads();
    for (int o = 128; o > 0; o >>= 1) { if (t < o) red[t] += red[t+o]; __syncthreads(); }
    if (t == 0) s_mu = red[0] / (float)HW;
    __syncthreads();
    const float mu = s_mu;

    float v = 0.f;
    for (int i = t; i < HW; i += 256) { const float d = p[i]-mu; v += d*d; }
    red[t] = v; __syncthreads();
    for (int o = 128; o > 0; o >>= 1) { if (t < o) red[t] += red[t+o]; __syncthreads(); }
    if (t == 0) s_rs = rsqrtf(red[0] / (float)HW + 1e-5f);
    __syncthreads();
    const float rs = s_rs;

    for (int i = t; i < HW; i += 256) {
        float val = (p[i] - mu) * rs;
        if (relu) val = fmaxf(val, 0.f);
        if (a) val += a[i];
        q[i] = val;
    }
}

// ---------------------------------------------------------------------------
// Reflect pad 32x32 -> 34x34 (pad 1, mirror excluding edge)
// ---------------------------------------------------------------------------
__global__ void __launch_bounds__(256)
pad_reflect_kernel(const float* __restrict__ in, float* __restrict__ out)
{
    constexpr int BC = 16*256;
    const int idx = blockIdx.x*blockDim.x + threadIdx.x;
    if (idx >= BC*34*34) return;
    const int x  = idx % 34;
    int tmp      = idx / 34;
    const int y  = tmp % 34;
    const int bc = tmp / 34;
    int iy = y - 1; if (iy < 0) iy = -iy; if (iy > 31) iy = 62 - iy;
    int ix = x - 1; if (ix < 0) ix = -ix; if (ix > 31) ix = 62 - ix;
    out[idx] = in[((size_t)bc*32 + iy)*32 + ix];
}

// ---------------------------------------------------------------------------
// Launch
// ---------------------------------------------------------------------------
extern "C" void kernel_launch(void* const* d_in, const int* in_sizes, int n_in,
                              void* d_out, int out_size)
{
    const float* x      = (const float*)d_in[0];
    const float* w_off1 = (const float*)d_in[1];
    const float* b_off1 = (const float*)d_in[2];
    const float* w1     = (const float*)d_in[3];
    const float* b1     = (const float*)d_in[4];
    const float* w_off2 = (const float*)d_in[5];
    const float* b_off2 = (const float*)d_in[6];
    const float* w2     = (const float*)d_in[7];
    const float* b2     = (const float*)d_in[8];
    const float* w_off3 = (const float*)d_in[9];
    const float* b_off3 = (const float*)d_in[10];
    const float* w3     = (const float*)d_in[11];
    const float* b3     = (const float*)d_in[12];
    const float* rw0a   = (const float*)d_in[13];
    const float* rb0a   = (const float*)d_in[14];
    const float* rw0b   = (const float*)d_in[15];
    const float* rb0b   = (const float*)d_in[16];
    const float* rw1a   = (const float*)d_in[17];
    const float* rb1a   = (const float*)d_in[18];
    const float* rw1b   = (const float*)d_in[19];
    const float* rb1b   = (const float*)d_in[20];

    float* out = (float*)d_out;
    float* out_h  = out;                                   // [16,256,32,32]
    float* out_s2 = out + 16*256*32*32;                    // [16,128,64,64]
    float* out_s3 = out + 16*256*32*32 + 16*128*64*64;     // [16,256,32,32]

    float *om1,*col1,*t1,*om2,*col2,*t2,*om3,*col3,*t3,*padb,*ybuf,*cvb,*hbuf;
    cudaGetSymbolAddress((void**)&om1,  g_om1);
    cudaGetSymbolAddress((void**)&col1, g_col1);
    cudaGetSymbolAddress((void**)&t1,   g_t1);
    cudaGetSymbolAddress((void**)&om2,  g_om2);
    cudaGetSymbolAddress((void**)&col2, g_col2);
    cudaGetSymbolAddress((void**)&t2,   g_t2);
    cudaGetSymbolAddress((void**)&om3,  g_om3);
    cudaGetSymbolAddress((void**)&col3, g_col3);
    cudaGetSymbolAddress((void**)&t3,   g_t3);
    cudaGetSymbolAddress((void**)&padb, g_pad);
    cudaGetSymbolAddress((void**)&ybuf, g_y);
    cudaGetSymbolAddress((void**)&cvb,  g_cv);
    cudaGetSymbolAddress((void**)&hbuf, g_h);

    // ------------------ Stage 1: 3 -> 64, 7x7, s1 p3, 128x128 ------------------
    {
        const int Ntot = 16*128*128;                         // 262144
        conv_gemm_kernel<3,128,128,7,7,1,3,128,128>
            <<<dim3(Ntot/64, (147+63)/64), 256>>>(x, w_off1, b_off1, om1, 147);

        const int tot = 16*49*128*128;
        deform_sample_kernel<3,128,128,7,7,1,3,128,128>
            <<<(tot+255)/256, 256>>>(x, om1, col1);

        conv_gemm_kernel<147,128,128,1,1,1,0,128,128>
            <<<dim3(Ntot/64, 1), 256>>>(col1, w1, b1, t1, 64);

        instnorm_kernel<<<16*64, 256>>>(t1, t1, nullptr, 128*128, 1);
    }

    // ------------------ Stage 2: 64 -> 128, 4x4, s2 p1, -> 64x64 ---------------
    {
        const int Ntot = 16*64*64;                           // 65536
        conv_gemm_kernel<64,128,128,4,4,2,1,64,64>
            <<<dim3(Ntot/64, 1), 256>>>(t1, w_off2, b_off2, om2, 48);

        const int tot = 16*16*64*64;
        deform_sample_kernel<64,128,128,4,4,2,1,64,64>
            <<<(tot+255)/256, 256>>>(t1, om2, col2);

        conv_gemm_kernel<1024,64,64,1,1,1,0,64,64>
            <<<dim3(Ntot/64, 2), 256>>>(col2, w2, b2, t2, 128);

        instnorm_kernel<<<16*128, 256>>>(t2, out_s2, nullptr, 64*64, 1);   // skip2
    }

    // ------------------ Stage 3: 128 -> 256, 4x4, s2 p1, -> 32x32 --------------
    {
        const int Ntot = 16*32*32;                           // 16384
        conv_gemm_kernel<128,64,64,4,4,2,1,32,32>
            <<<dim3(Ntot/64, 1), 256>>>(out_s2, w_off3, b_off3, om3, 48);

        const int tot = 16*16*32*32;
        deform_sample_kernel<128,64,64,4,4,2,1,32,32>
            <<<(tot+255)/256, 256>>>(out_s2, om3, col3);

        conv_gemm_kernel<2048,32,32,1,1,1,0,32,32>
            <<<dim3(Ntot/64, 4), 256>>>(col3, w3, b3, t3, 256);

        instnorm_kernel<<<16*256, 256>>>(t3, out_s3, nullptr, 32*32, 1);   // skip3
    }

    // ------------------ Residual blocks on [16,256,32,32] ----------------------
    const int Npix   = 16*32*32;                             // 16384
    const int padTot = 16*256*34*34;
    const dim3 cgrid(Npix/64, 4);

    // block 0: input = skip3 (read from d_out region)
    pad_reflect_kernel<<<(padTot+255)/256, 256>>>(out_s3, padb);
    conv_gemm_kernel<256,34,34,3,3,1,0,32,32><<<cgrid, 256>>>(padb, rw0a, rb0a, cvb, 256);
    instnorm_kernel<<<16*256, 256>>>(cvb, ybuf, nullptr, 32*32, 1);
    pad_reflect_kernel<<<(padTot+255)/256, 256>>>(ybuf, padb);
    conv_gemm_kernel<256,34,34,3,3,1,0,32,32><<<cgrid, 256>>>(padb, rw0b, rb0b, cvb, 256);
    instnorm_kernel<<<16*256, 256>>>(cvb, hbuf, out_s3, 32*32, 0);   // h = skip3 + IN(conv)

    // block 1: input = hbuf
    pad_reflect_kernel<<<(padTot+255)/256, 256>>>(hbuf, padb);
    conv_gemm_kernel<256,34,34,3,3,1,0,32,32><<<cgrid, 256>>>(padb, rw1a, rb1a, cvb, 256);
    instnorm_kernel<<<16*256, 256>>>(cvb, ybuf, nullptr, 32*32, 1);
    pad_reflect_kernel<<<(padTot+255)/256, 256>>>(ybuf, padb);
    conv_gemm_kernel<256,34,34,3,3,1,0,32,32><<<cgrid, 256>>>(padb, rw1b, rb1b, cvb, 256);
    instnorm_kernel<<<16*256, 256>>>(cvb, out_h, hbuf, 32*32, 0);    // final h
}

// round 3
// speedup vs baseline: 1.1549x; 1.1549x over previous
#include <cuda_runtime.h>
#include <math.h>

// ---------------------------------------------------------------------------
// Scratch (__device__ globals)
// ---------------------------------------------------------------------------
__device__ float g_om1 [16*147*128*128];
__device__ float g_col1[16*147*128*128];
__device__ float g_t1  [16*64*128*128];
__device__ float g_om2 [16*48*64*64];
__device__ float g_col2[16*1024*64*64];
__device__ float g_t2  [16*128*64*64];
__device__ float g_om3 [16*48*32*32];
__device__ float g_col3[16*2048*32*32];
__device__ float g_t3  [16*256*32*32];
__device__ float g_y   [16*256*32*32];
__device__ float g_cv  [16*256*32*32];
__device__ float g_h   [16*256*32*32];

// ---------------------------------------------------------------------------
// Packed fp32x2 helpers (sm_100+ PTX)
// ---------------------------------------------------------------------------
__device__ __forceinline__ unsigned long long packdup(float x){
    unsigned long long d;
    asm("mov.b64 %0, {%1, %1};" : "=l"(d) : "f"(x));
    return d;
}
__device__ __forceinline__ void fma2(unsigned long long& d, unsigned long long a,
                                     unsigned long long b){
    asm("fma.rn.f32x2 %0, %1, %2, %0;" : "+l"(d) : "l"(a), "l"(b));
}
__device__ __forceinline__ float2 unpack2(unsigned long long v){
    float2 r;
    asm("mov.b64 {%0, %1}, %2;" : "=f"(r.x), "=f"(r.y) : "l"(v));
    return r;
}

// ---------------------------------------------------------------------------
// Conv-as-GEMM with on-the-fly im2col, FFMA2 microkernel.
// BN=128 fixed, BK=16. BM = 128 (8x8 microtile) or 64 (4x8 microtile).
// REFLECT=1: reflect-pad border rule (for the residual 3x3 convs).
// out[b,m,pix] = bias[m] + sum_k W[m,k] * im2col(in)[k, b*HW+pix]
// ---------------------------------------------------------------------------
template<int CIN,int H,int W,int KH,int KW,int STR,int PAD,int HO,int WO,int BM,int REFLECT>
__global__ void __launch_bounds__(256,2)
conv_gemm(const float* __restrict__ in, const float* __restrict__ Wt,
          const float* __restrict__ bias, float* __restrict__ out, int M)
{
    constexpr int Kdim = CIN*KH*KW;
    constexpr int HW   = HO*WO;
    constexpr int BK = 16, BN = 128;
    constexpr int TM = BM/16;        // 8 or 4 rows per thread
    constexpr int VM = TM/4;         // 2 or 1 m-vectors
    constexpr int MP = TM/2;         // 4 or 2 m-pairs

    __shared__ __align__(16) float As[BK][BM+4];
    __shared__ __align__(16) float Bs[BK][BN];

    const int t     = threadIdx.x;
    const int nTile = blockIdx.x * BN;
    const int mTile = blockIdx.y * BM;
    const int tIdn  = t & 15;
    const int tIdm  = t >> 4;

    unsigned long long acc[MP][8];
    #pragma unroll
    for (int i = 0; i < MP; i++)
        #pragma unroll
        for (int j = 0; j < 8; j++) acc[i][j] = 0ull;

    for (int k0 = 0; k0 < Kdim; k0 += BK) {
        // ---- A tile (weights, transposed into [k][m]) ----
        #pragma unroll
        for (int i = 0; i < (BM*BK)/256; i++) {
            const int e = i*256 + t;
            const int k = e & 15;
            const int m = e >> 4;
            float v = 0.f;
            if (k0 + k < Kdim && mTile + m < M)
                v = Wt[(size_t)(mTile + m)*Kdim + (k0 + k)];
            As[k][m] = v;
        }
        // ---- B tile (im2col gather) ----
        #pragma unroll
        for (int i = 0; i < 8; i++) {
            const int e  = i*256 + t;
            const int nl = e & 127;
            const int kk = e >> 7;
            const int k  = k0 + kk;
            float v = 0.f;
            if (k < Kdim) {
                const int n   = nTile + nl;
                const int b   = n / HW;
                const int rem = n % HW;
                const int oy  = rem / WO;
                const int ox  = rem % WO;
                const int ci  = k / (KH*KW);
                const int r   = k % (KH*KW);
                const int ky  = r / KW;
                const int kx  = r % KW;
                int iy = oy*STR - PAD + ky;
                int ix = ox*STR - PAD + kx;
                if (REFLECT) {
                    iy = iy < 0 ? -iy : (iy >= H ? 2*H - 2 - iy : iy);
                    ix = ix < 0 ? -ix : (ix >= W ? 2*W - 2 - ix : ix);
                    v = in[((size_t)(b*CIN + ci)*H + iy)*W + ix];
                } else {
                    if (iy >= 0 && iy < H && ix >= 0 && ix < W)
                        v = in[((size_t)(b*CIN + ci)*H + iy)*W + ix];
                }
            }
            Bs[kk][nl] = v;
        }
        __syncthreads();

        #pragma unroll
        for (int kk = 0; kk < BK; kk++) {
            unsigned long long ap[MP];
            #pragma unroll
            for (int v = 0; v < VM; v++) {
                const ulonglong2 av =
                    *reinterpret_cast<const ulonglong2*>(&As[kk][v*(BM/2) + tIdm*4]);
                ap[v*2]   = av.x;
                ap[v*2+1] = av.y;
            }
            #pragma unroll
            for (int v = 0; v < 2; v++) {
                const float4 bv =
                    *reinterpret_cast<const float4*>(&Bs[kk][v*64 + tIdn*4]);
                const unsigned long long b0 = packdup(bv.x);
                const unsigned long long b1 = packdup(bv.y);
                const unsigned long long b2 = packdup(bv.z);
                const unsigned long long b3 = packdup(bv.w);
                #pragma unroll
                for (int i = 0; i < MP; i++) {
                    fma2(acc[i][v*4+0], ap[i], b0);
                    fma2(acc[i][v*4+1], ap[i], b1);
                    fma2(acc[i][v*4+2], ap[i], b2);
                    fma2(acc[i][v*4+3], ap[i], b3);
                }
            }
        }
        __syncthreads();
    }

    // ---- epilogue ----
    #pragma unroll
    for (int i = 0; i < MP; i++) {
        const int m0 = mTile + (i >> 1)*(BM/2) + tIdm*4 + (i & 1)*2;
        const bool v0 = (m0     < M);
        const bool v1 = (m0 + 1 < M);
        const float bia0 = v0 ? bias[m0]     : 0.f;
        const float bia1 = v1 ? bias[m0 + 1] : 0.f;
        #pragma unroll
        for (int j = 0; j < 8; j++) {
            const int n  = nTile + (j >> 2)*64 + tIdn*4 + (j & 3);
            const int b2 = n / HW;
            const int r2 = n % HW;
            const float2 p = unpack2(acc[i][j]);
            if (v0) out[((size_t)b2*M + m0    )*HW + r2] = p.x + bia0;
            if (v1) out[((size_t)b2*M + m0 + 1)*HW + r2] = p.y + bia1;
        }
    }
}

// ---------------------------------------------------------------------------
// DCNv2 sampling: col[b, ci*K + k, pix] = mask * bilinear(x[b,ci], ys, xs)
// ---------------------------------------------------------------------------
template<int CIN,int H,int W,int KH,int KW,int STR,int PAD,int HO,int WO>
__global__ void __launch_bounds__(256)
deform_sample_kernel(const float* __restrict__ x, const float* __restrict__ om,
                     float* __restrict__ col)
{
    constexpr int B  = 16;
    constexpr int K  = KH*KW;
    constexpr int HW = HO*WO;

    const int idx = blockIdx.x*blockDim.x + threadIdx.x;
    if (idx >= B*K*HW) return;

    const int ox  = idx % WO;
    int tmp       = idx / WO;
    const int oy  = tmp % HO;  tmp /= HO;
    const int k   = tmp % K;
    const int b   = tmp / K;
    const int ky  = k / KW;
    const int kx  = k % KW;

    const int pix = oy*WO + ox;
    const float offy = om[((size_t)(b*3*K + 2*k    )*HW) + pix];
    const float offx = om[((size_t)(b*3*K + 2*k + 1)*HW) + pix];
    const float mv   = om[((size_t)(b*3*K + 2*K + k)*HW) + pix];
    const float mask = 1.f / (1.f + expf(-mv));

    const float ys = (float)(oy*STR - PAD + ky) + offy;
    const float xs = (float)(ox*STR - PAD + kx) + offx;

    const float y0f = floorf(ys), x0f = floorf(xs);
    const float dy = ys - y0f,    dx = xs - x0f;
    const int y0 = (int)y0f, x0 = (int)x0f;
    const int y1 = y0 + 1,   x1 = x0 + 1;

    const bool vy0 = (y0 >= 0) & (y0 < H);
    const bool vy1 = (y1 >= 0) & (y1 < H);
    const bool vx0 = (x0 >= 0) & (x0 < W);
    const bool vx1 = (x1 >= 0) & (x1 < W);

    const int cy0 = min(max(y0, 0), H-1), cy1 = min(max(y1, 0), H-1);
    const int cx0 = min(max(x0, 0), W-1), cx1 = min(max(x1, 0), W-1);

    const float f00 = (vy0 && vx0) ? (1.f-dy)*(1.f-dx)*mask : 0.f;
    const float f01 = (vy0 && vx1) ? (1.f-dy)*dx*mask       : 0.f;
    const float f10 = (vy1 && vx0) ? dy*(1.f-dx)*mask       : 0.f;
    const float f11 = (vy1 && vx1) ? dy*dx*mask             : 0.f;

    const int i00 = cy0*W + cx0, i01 = cy0*W + cx1;
    const int i10 = cy1*W + cx0, i11 = cy1*W + cx1;

    const float* xb = x + (size_t)b*CIN*H*W;
    float* cp = col + (((size_t)b*CIN*K + k)*HW) + pix;

    #pragma unroll 4
    for (int ci = 0; ci < CIN; ci++) {
        const float* img = xb + (size_t)ci*H*W;
        const float v = f00*img[i00] + f01*img[i01] + f10*img[i10] + f11*img[i11];
        cp[(size_t)ci*K*HW] = v;
    }
}

// ---------------------------------------------------------------------------
// Instance norm (two-pass) + optional ReLU + optional residual add.
// ---------------------------------------------------------------------------
__global__ void __launch_bounds__(256)
instnorm_kernel(const float* __restrict__ in, float* __restrict__ out,
                const float* __restrict__ addsrc, int HW, int relu)
{
    const int bc = blockIdx.x;
    const float* p = in + (size_t)bc*HW;
    float* q = out + (size_t)bc*HW;
    const float* a = addsrc ? addsrc + (size_t)bc*HW : nullptr;

    __shared__ float red[256];
    __shared__ float s_mu, s_rs;
    const int t = threadIdx.x;

    float s = 0.f;
    for (int i = t; i < HW; i += 256) s += p[i];
    red[t] = s; __syncthreads();
    for (int o = 128; o > 0; o >>= 1) { if (t < o) red[t] += red[t+o]; __syncthreads(); }
    if (t == 0) s_mu = red[0] / (float)HW;
    __syncthreads();
    const float mu = s_mu;

    float v = 0.f;
    for (int i = t; i < HW; i += 256) { const float d = p[i]-mu; v += d*d; }
    red[t] = v; __syncthreads();
    for (int o = 128; o > 0; o >>= 1) { if (t < o) red[t] += red[t+o]; __syncthreads(); }
    if (t == 0) s_rs = rsqrtf(red[0] / (float)HW + 1e-5f);
    __syncthreads();
    const float rs = s_rs;

    for (int i = t; i < HW; i += 256) {
        float val = (p[i] - mu) * rs;
        if (relu) val = fmaxf(val, 0.f);
        if (a) val += a[i];
        q[i] = val;
    }
}

// ---------------------------------------------------------------------------
// Launch
// ---------------------------------------------------------------------------
extern "C" void kernel_launch(void* const* d_in, const int* in_sizes, int n_in,
                              void* d_out, int out_size)
{
    const float* x      = (const float*)d_in[0];
    const float* w_off1 = (const float*)d_in[1];
    const float* b_off1 = (const float*)d_in[2];
    const float* w1     = (const float*)d_in[3];
    const float* b1     = (const float*)d_in[4];
    const float* w_off2 = (const float*)d_in[5];
    const float* b_off2 = (const float*)d_in[6];
    const float* w2     = (const float*)d_in[7];
    const float* b2     = (const float*)d_in[8];
    const float* w_off3 = (const float*)d_in[9];
    const float* b_off3 = (const float*)d_in[10];
    const float* w3     = (const float*)d_in[11];
    const float* b3     = (const float*)d_in[12];
    const float* rw0a   = (const float*)d_in[13];
    const float* rb0a   = (const float*)d_in[14];
    const float* rw0b   = (const float*)d_in[15];
    const float* rb0b   = (const float*)d_in[16];
    const float* rw1a   = (const float*)d_in[17];
    const float* rb1a   = (const float*)d_in[18];
    const float* rw1b   = (const float*)d_in[19];
    const float* rb1b   = (const float*)d_in[20];

    float* out = (float*)d_out;
    float* out_h  = out;                                   // [16,256,32,32]
    float* out_s2 = out + 16*256*32*32;                    // [16,128,64,64]
    float* out_s3 = out + 16*256*32*32 + 16*128*64*64;     // [16,256,32,32]

    float *om1,*col1,*t1,*om2,*col2,*t2,*om3,*col3,*t3,*ybuf,*cvb,*hbuf;
    cudaGetSymbolAddress((void**)&om1,  g_om1);
    cudaGetSymbolAddress((void**)&col1, g_col1);
    cudaGetSymbolAddress((void**)&t1,   g_t1);
    cudaGetSymbolAddress((void**)&om2,  g_om2);
    cudaGetSymbolAddress((void**)&col2, g_col2);
    cudaGetSymbolAddress((void**)&t2,   g_t2);
    cudaGetSymbolAddress((void**)&om3,  g_om3);
    cudaGetSymbolAddress((void**)&col3, g_col3);
    cudaGetSymbolAddress((void**)&t3,   g_t3);
    cudaGetSymbolAddress((void**)&ybuf, g_y);
    cudaGetSymbolAddress((void**)&cvb,  g_cv);
    cudaGetSymbolAddress((void**)&hbuf, g_h);

    // ------------------ Stage 1: 3 -> 64, 7x7, s1 p3, 128x128 ------------------
    {
        conv_gemm<3,128,128,7,7,1,3,128,128,64,0>
            <<<dim3(2048, 3), 256>>>(x, w_off1, b_off1, om1, 147);

        const int tot = 16*49*128*128;
        deform_sample_kernel<3,128,128,7,7,1,3,128,128>
            <<<(tot+255)/256, 256>>>(x, om1, col1);

        conv_gemm<147,128,128,1,1,1,0,128,128,64,0>
            <<<dim3(2048, 1), 256>>>(col1, w1, b1, t1, 64);

        instnorm_kernel<<<16*64, 256>>>(t1, t1, nullptr, 128*128, 1);
    }

    // ------------------ Stage 2: 64 -> 128, 4x4, s2 p1, -> 64x64 ---------------
    {
        conv_gemm<64,128,128,4,4,2,1,64,64,64,0>
            <<<dim3(512, 1), 256>>>(t1, w_off2, b_off2, om2, 48);

        const int tot = 16*16*64*64;
        deform_sample_kernel<64,128,128,4,4,2,1,64,64>
            <<<(tot+255)/256, 256>>>(t1, om2, col2);

        conv_gemm<1024,64,64,1,1,1,0,64,64,128,0>
            <<<dim3(512, 1), 256>>>(col2, w2, b2, t2, 128);

        instnorm_kernel<<<16*128, 256>>>(t2, out_s2, nullptr, 64*64, 1);   // skip2
    }

    // ------------------ Stage 3: 128 -> 256, 4x4, s2 p1, -> 32x32 --------------
    {
        conv_gemm<128,64,64,4,4,2,1,32,32,64,0>
            <<<dim3(128, 1), 256>>>(out_s2, w_off3, b_off3, om3, 48);

        const int tot = 16*16*32*32;
        deform_sample_kernel<128,64,64,4,4,2,1,32,32>
            <<<(tot+255)/256, 256>>>(out_s2, om3, col3);

        conv_gemm<2048,32,32,1,1,1,0,32,32,128,0>
            <<<dim3(128, 2), 256>>>(col3, w3, b3, t3, 256);

        instnorm_kernel<<<16*256, 256>>>(t3, out_s3, nullptr, 32*32, 1);   // skip3
    }

    // ------------------ Residual blocks on [16,256,32,32] ----------------------
    const dim3 cgrid(128, 2);

    // block 0: input = skip3 (reads d_out region)
    conv_gemm<256,32,32,3,3,1,1,32,32,128,1><<<cgrid, 256>>>(out_s3, rw0a, rb0a, cvb, 256);
    instnorm_kernel<<<16*256, 256>>>(cvb, ybuf, nullptr, 32*32, 1);
    conv_gemm<256,32,32,3,3,1,1,32,32,128,1><<<cgrid, 256>>>(ybuf, rw0b, rb0b, cvb, 256);
    instnorm_kernel<<<16*256, 256>>>(cvb, hbuf, out_s3, 32*32, 0);   // h = skip3 + IN(conv)

    // block 1: input = hbuf
    conv_gemm<256,32,32,3,3,1,1,32,32,128,1><<<cgrid, 256>>>(hbuf, rw1a, rb1a, cvb, 256);
    instnorm_kernel<<<16*256, 256>>>(cvb, ybuf, nullptr, 32*32, 1);
    conv_gemm<256,32,32,3,3,1,1,32,32,128,1><<<cgrid, 256>>>(ybuf, rw1b, rb1b, cvb, 256);
    instnorm_kernel<<<16*256, 256>>>(cvb, out_h, hbuf, 32*32, 0);    // final h
}

// round 4
// speedup vs baseline: 1.2004x; 1.0395x over previous
#include <cuda_runtime.h>
#include <math.h>

// ---------------------------------------------------------------------------
// Scratch (__device__ globals)
// ---------------------------------------------------------------------------
__device__ float g_om1 [16*147*128*128];
__device__ float g_col1[16*147*128*128];
__device__ float g_t1  [16*64*128*128];
__device__ float g_om2 [16*48*64*64];
__device__ float g_col2[16*1024*64*64];
__device__ float g_t2  [16*128*64*64];
__device__ float g_om3 [16*48*32*32];
__device__ float g_col3[16*2048*32*32];
__device__ float g_t3  [16*256*32*32];
__device__ float g_y   [16*256*32*32];
__device__ float g_cv  [16*256*32*32];
__device__ float g_h   [16*256*32*32];

// ---------------------------------------------------------------------------
// Packed fp32x2 helpers (sm_100+ PTX)
// ---------------------------------------------------------------------------
__device__ __forceinline__ unsigned long long packdup(float x){
    unsigned long long d;
    asm("mov.b64 %0, {%1, %1};" : "=l"(d) : "f"(x));
    return d;
}
__device__ __forceinline__ void fma2(unsigned long long& d, unsigned long long a,
                                     unsigned long long b){
    asm("fma.rn.f32x2 %0, %1, %2, %0;" : "+l"(d) : "l"(a), "l"(b));
}
__device__ __forceinline__ float2 unpack2(unsigned long long v){
    float2 r;
    asm("mov.b64 {%0, %1}, %2;" : "=f"(r.x), "=f"(r.y) : "l"(v));
    return r;
}

// ---------------------------------------------------------------------------
// Conv-as-GEMM, FFMA2 microkernel, 2-stage smem double buffering.
// BN=128, BK=16. BM = 128 (8x8 microtile) or 64 (4x8).
// One __syncthreads per K-slab; LDG of slab i+1 overlaps compute of slab i.
// ---------------------------------------------------------------------------
template<int CIN,int H,int W,int KH,int KW,int STR,int PAD,int HO,int WO,int BM,int REFLECT>
__global__ void __launch_bounds__(256,2)
conv_gemm(const float* __restrict__ in, const float* __restrict__ Wt,
          const float* __restrict__ bias, float* __restrict__ out, int M)
{
    constexpr int Kdim = CIN*KH*KW;
    constexpr int HW   = HO*WO;
    constexpr int BK = 16, BN = 128;
    constexpr int TM = BM/16;
    constexpr int VM = TM/4;
    constexpr int MP = TM/2;
    constexpr int AR = (BM*BK)/256;               // A elements per thread
    constexpr int NT = (Kdim + BK - 1)/BK;        // K slabs

    __shared__ __align__(16) float As[2][BK][BM+4];
    __shared__ __align__(16) float Bs[2][BK][BN];

    const int t     = threadIdx.x;
    const int nTile = blockIdx.x * BN;
    const int mTile = blockIdx.y * BM;
    const int tIdn  = t & 15;
    const int tIdm  = t >> 4;

    // ---- B-gather loop invariants: thread always serves column nl ----
    const int nl   = t & 127;
    const int kb0  = t >> 7;                      // covers k rows kb0 + 2*i
    const int n    = nTile + nl;
    const int b    = n / HW;
    const int rem  = n % HW;
    const int oy   = rem / WO;
    const int ox   = rem % WO;
    const int iy0  = oy*STR - PAD;
    const int ix0  = ox*STR - PAD;
    const float* inb = in + (size_t)b*CIN*H*W;

    // ---- A-load invariants ----
    const int ka  = t & 15;
    const int ma0 = t >> 4;

    float regA[AR];
    float regB[8];

    auto loadA = [&](int k0){
        #pragma unroll
        for (int i = 0; i < AR; i++) {
            const int m = mTile + ma0 + i*16;
            const int k = k0 + ka;
            float v = 0.f;
            if (k < Kdim && m < M) v = Wt[(size_t)m*Kdim + k];
            regA[i] = v;
        }
    };
    auto loadB = [&](int k0){
        #pragma unroll
        for (int i = 0; i < 8; i++) {
            const int k = k0 + kb0 + i*2;
            float v = 0.f;
            if (k < Kdim) {
                const int ci = k / (KH*KW);
                const int r  = k % (KH*KW);
                const int ky = r / KW;
                const int kx = r % KW;
                int iy = iy0 + ky;
                int ix = ix0 + kx;
                if (REFLECT) {
                    iy = iy < 0 ? -iy : (iy >= H ? 2*H-2-iy : iy);
                    ix = ix < 0 ? -ix : (ix >= W ? 2*W-2-ix : ix);
                    v = inb[((size_t)ci*H + iy)*W + ix];
                } else if (iy >= 0 && iy < H && ix >= 0 && ix < W) {
                    v = inb[((size_t)ci*H + iy)*W + ix];
                }
            }
            regB[i] = v;
        }
    };
    auto storeA = [&](int buf){
        #pragma unroll
        for (int i = 0; i < AR; i++) As[buf][ka][ma0 + i*16] = regA[i];
    };
    auto storeB = [&](int buf){
        #pragma unroll
        for (int i = 0; i < 8; i++) Bs[buf][kb0 + i*2][nl] = regB[i];
    };

    unsigned long long acc[MP][8];
    #pragma unroll
    for (int i = 0; i < MP; i++)
        #pragma unroll
        for (int j = 0; j < 8; j++) acc[i][j] = 0ull;

    // prologue
    loadA(0); loadB(0);
    storeA(0); storeB(0);
    __syncthreads();

    for (int it = 0; it < NT; it++) {
        const int cur = it & 1;
        const int nxt = cur ^ 1;
        const bool more = (it + 1 < NT);
        if (more) { loadA((it+1)*BK); loadB((it+1)*BK); }

        #pragma unroll
        for (int kk = 0; kk < BK; kk++) {
            unsigned long long ap[MP];
            #pragma unroll
            for (int v = 0; v < VM; v++) {
                const ulonglong2 av =
                    *reinterpret_cast<const ulonglong2*>(&As[cur][kk][v*(BM/2) + tIdm*4]);
                ap[v*2]   = av.x;
                ap[v*2+1] = av.y;
            }
            #pragma unroll
            for (int v = 0; v < 2; v++) {
                const float4 bv =
                    *reinterpret_cast<const float4*>(&Bs[cur][kk][v*64 + tIdn*4]);
                const unsigned long long b0 = packdup(bv.x);
                const unsigned long long b1 = packdup(bv.y);
                const unsigned long long b2 = packdup(bv.z);
                const unsigned long long b3 = packdup(bv.w);
                #pragma unroll
                for (int i = 0; i < MP; i++) {
                    fma2(acc[i][v*4+0], ap[i], b0);
                    fma2(acc[i][v*4+1], ap[i], b1);
                    fma2(acc[i][v*4+2], ap[i], b2);
                    fma2(acc[i][v*4+3], ap[i], b3);
                }
            }
        }

        if (more) { storeA(nxt); storeB(nxt); }
        __syncthreads();
    }

    // ---- epilogue ----
    #pragma unroll
    for (int i = 0; i < MP; i++) {
        const int m0 = mTile + (i >> 1)*(BM/2) + tIdm*4 + (i & 1)*2;
        const bool v0 = (m0     < M);
        const bool v1 = (m0 + 1 < M);
        const float bia0 = v0 ? bias[m0]     : 0.f;
        const float bia1 = v1 ? bias[m0 + 1] : 0.f;
        #pragma unroll
        for (int j = 0; j < 8; j++) {
            const int nn = nTile + (j >> 2)*64 + tIdn*4 + (j & 3);
            const int b2 = nn / HW;
            const int r2 = nn % HW;
            const float2 p = unpack2(acc[i][j]);
            if (v0) out[((size_t)b2*M + m0    )*HW + r2] = p.x + bia0;
            if (v1) out[((size_t)b2*M + m0 + 1)*HW + r2] = p.y + bia1;
        }
    }
}

// ---------------------------------------------------------------------------
// DCNv2 sampling: col[b, ci*K + k, pix] = mask * bilinear(x[b,ci], ys, xs)
// ---------------------------------------------------------------------------
template<int CIN,int H,int W,int KH,int KW,int STR,int PAD,int HO,int WO>
__global__ void __launch_bounds__(256)
deform_sample_kernel(const float* __restrict__ x, const float* __restrict__ om,
                     float* __restrict__ col)
{
    constexpr int B  = 16;
    constexpr int K  = KH*KW;
    constexpr int HW = HO*WO;

    const int idx = blockIdx.x*blockDim.x + threadIdx.x;
    if (idx >= B*K*HW) return;

    const int ox  = idx % WO;
    int tmp       = idx / WO;
    const int oy  = tmp % HO;  tmp /= HO;
    const int k   = tmp % K;
    const int b   = tmp / K;
    const int ky  = k / KW;
    const int kx  = k % KW;

    const int pix = oy*WO + ox;
    const float offy = om[((size_t)(b*3*K + 2*k    )*HW) + pix];
    const float offx = om[((size_t)(b*3*K + 2*k + 1)*HW) + pix];
    const float mv   = om[((size_t)(b*3*K + 2*K + k)*HW) + pix];
    const float mask = 1.f / (1.f + expf(-mv));

    const float ys = (float)(oy*STR - PAD + ky) + offy;
    const float xs = (float)(ox*STR - PAD + kx) + offx;

    const float y0f = floorf(ys), x0f = floorf(xs);
    const float dy = ys - y0f,    dx = xs - x0f;
    const int y0 = (int)y0f, x0 = (int)x0f;
    const int y1 = y0 + 1,   x1 = x0 + 1;

    const bool vy0 = (y0 >= 0) & (y0 < H);
    const bool vy1 = (y1 >= 0) & (y1 < H);
    const bool vx0 = (x0 >= 0) & (x0 < W);
    const bool vx1 = (x1 >= 0) & (x1 < W);

    const int cy0 = min(max(y0, 0), H-1), cy1 = min(max(y1, 0), H-1);
    const int cx0 = min(max(x0, 0), W-1), cx1 = min(max(x1, 0), W-1);

    const float f00 = (vy0 && vx0) ? (1.f-dy)*(1.f-dx)*mask : 0.f;
    const float f01 = (vy0 && vx1) ? (1.f-dy)*dx*mask       : 0.f;
    const float f10 = (vy1 && vx0) ? dy*(1.f-dx)*mask       : 0.f;
    const float f11 = (vy1 && vx1) ? dy*dx*mask             : 0.f;

    const int i00 = cy0*W + cx0, i01 = cy0*W + cx1;
    const int i10 = cy1*W + cx0, i11 = cy1*W + cx1;

    const float* xb = x + (size_t)b*CIN*H*W;
    float* cp = col + (((size_t)b*CIN*K + k)*HW) + pix;

    #pragma unroll 4
    for (int ci = 0; ci < CIN; ci++) {
        const float* img = xb + (size_t)ci*H*W;
        const float v = f00*img[i00] + f01*img[i01] + f10*img[i10] + f11*img[i11];
        cp[(size_t)ci*K*HW] = v;
    }
}

// ---------------------------------------------------------------------------
// Instance norm (two-pass) + optional ReLU + optional residual add.
// ---------------------------------------------------------------------------
__global__ void __launch_bounds__(256)
instnorm_kernel(const float* __restrict__ in, float* __restrict__ out,
                const float* __restrict__ addsrc, int HW, int relu)
{
    const int bc = blockIdx.x;
    const float* p = in + (size_t)bc*HW;
    float* q = out + (size_t)bc*HW;
    const float* a = addsrc ? addsrc + (size_t)bc*HW : nullptr;

    __shared__ float red[256];
    __shared__ float s_mu, s_rs;
    const int t = threadIdx.x;

    float s = 0.f;
    for (int i = t; i < HW; i += 256) s += p[i];
    red[t] = s; __syncthreads();
    for (int o = 128; o > 0; o >>= 1) { if (t < o) red[t] += red[t+o]; __syncthreads(); }
    if (t == 0) s_mu = red[0] / (float)HW;
    __syncthreads();
    const float mu = s_mu;

    float v = 0.f;
    for (int i = t; i < HW; i += 256) { const float d = p[i]-mu; v += d*d; }
    red[t] = v; __syncthreads();
    for (int o = 128; o > 0; o >>= 1) { if (t < o) red[t] += red[t+o]; __syncthreads(); }
    if (t == 0) s_rs = rsqrtf(red[0] / (float)HW + 1e-5f);
    __syncthreads();
    const float rs = s_rs;

    for (int i = t; i < HW; i += 256) {
        float val = (p[i] - mu) * rs;
        if (relu) val = fmaxf(val, 0.f);
        if (a) val += a[i];
        q[i] = val;
    }
}

// ---------------------------------------------------------------------------
// Launch
// ---------------------------------------------------------------------------
extern "C" void kernel_launch(void* const* d_in, const int* in_sizes, int n_in,
                              void* d_out, int out_size)
{
    const float* x      = (const float*)d_in[0];
    const float* w_off1 = (const float*)d_in[1];
    const float* b_off1 = (const float*)d_in[2];
    const float* w1     = (const float*)d_in[3];
    const float* b1     = (const float*)d_in[4];
    const float* w_off2 = (const float*)d_in[5];
    const float* b_off2 = (const float*)d_in[6];
    const float* w2     = (const float*)d_in[7];
    const float* b2     = (const float*)d_in[8];
    const float* w_off3 = (const float*)d_in[9];
    const float* b_off3 = (const float*)d_in[10];
    const float* w3     = (const float*)d_in[11];
    const float* b3     = (const float*)d_in[12];
    const float* rw0a   = (const float*)d_in[13];
    const float* rb0a   = (const float*)d_in[14];
    const float* rw0b   = (const float*)d_in[15];
    const float* rb0b   = (const float*)d_in[16];
    const float* rw1a   = (const float*)d_in[17];
    const float* rb1a   = (const float*)d_in[18];
    const float* rw1b   = (const float*)d_in[19];
    const float* rb1b   = (const float*)d_in[20];

    float* out = (float*)d_out;
    float* out_h  = out;                                   // [16,256,32,32]
    float* out_s2 = out + 16*256*32*32;                    // [16,128,64,64]
    float* out_s3 = out + 16*256*32*32 + 16*128*64*64;     // [16,256,32,32]

    float *om1,*col1,*t1,*om2,*col2,*t2,*om3,*col3,*t3,*ybuf,*cvb,*hbuf;
    cudaGetSymbolAddress((void**)&om1,  g_om1);
    cudaGetSymbolAddress((void**)&col1, g_col1);
    cudaGetSymbolAddress((void**)&t1,   g_t1);
    cudaGetSymbolAddress((void**)&om2,  g_om2);
    cudaGetSymbolAddress((void**)&col2, g_col2);
    cudaGetSymbolAddress((void**)&t2,   g_t2);
    cudaGetSymbolAddress((void**)&om3,  g_om3);
    cudaGetSymbolAddress((void**)&col3, g_col3);
    cudaGetSymbolAddress((void**)&t3,   g_t3);
    cudaGetSymbolAddress((void**)&ybuf, g_y);
    cudaGetSymbolAddress((void**)&cvb,  g_cv);
    cudaGetSymbolAddress((void**)&hbuf, g_h);

    // ------------------ Stage 1: 3 -> 64, 7x7, s1 p3, 128x128 ------------------
    {
        conv_gemm<3,128,128,7,7,1,3,128,128,64,0>
            <<<dim3(2048, 3), 256>>>(x, w_off1, b_off1, om1, 147);

        const int tot = 16*49*128*128;
        deform_sample_kernel<3,128,128,7,7,1,3,128,128>
            <<<(tot+255)/256, 256>>>(x, om1, col1);

        conv_gemm<147,128,128,1,1,1,0,128,128,64,0>
            <<<dim3(2048, 1), 256>>>(col1, w1, b1, t1, 64);

        instnorm_kernel<<<16*64, 256>>>(t1, t1, nullptr, 128*128, 1);
    }

    // ------------------ Stage 2: 64 -> 128, 4x4, s2 p1, -> 64x64 ---------------
    {
        conv_gemm<64,128,128,4,4,2,1,64,64,64,0>
            <<<dim3(512, 1), 256>>>(t1, w_off2, b_off2, om2, 48);

        const int tot = 16*16*64*64;
        deform_sample_kernel<64,128,128,4,4,2,1,64,64>
            <<<(tot+255)/256, 256>>>(t1, om2, col2);

        conv_gemm<1024,64,64,1,1,1,0,64,64,128,0>
            <<<dim3(512, 1), 256>>>(col2, w2, b2, t2, 128);

        instnorm_kernel<<<16*128, 256>>>(t2, out_s2, nullptr, 64*64, 1);   // skip2
    }

    // ------------------ Stage 3: 128 -> 256, 4x4, s2 p1, -> 32x32 --------------
    {
        conv_gemm<128,64,64,4,4,2,1,32,32,64,0>
            <<<dim3(128, 1), 256>>>(out_s2, w_off3, b_off3, om3, 48);

        const int tot = 16*16*32*32;
        deform_sample_kernel<128,64,64,4,4,2,1,32,32>
            <<<(tot+255)/256, 256>>>(out_s2, om3, col3);

        conv_gemm<2048,32,32,1,1,1,0,32,32,128,0>
            <<<dim3(128, 2), 256>>>(col3, w3, b3, t3, 256);

        instnorm_kernel<<<16*256, 256>>>(t3, out_s3, nullptr, 32*32, 1);   // skip3
    }

    // ------------------ Residual blocks on [16,256,32,32] ----------------------
    const dim3 cgrid(128, 2);

    // block 0: input = skip3 (reads d_out region)
    conv_gemm<256,32,32,3,3,1,1,32,32,128,1><<<cgrid, 256>>>(out_s3, rw0a, rb0a, cvb, 256);
    instnorm_kernel<<<16*256, 256>>>(cvb, ybuf, nullptr, 32*32, 1);
    conv_gemm<256,32,32,3,3,1,1,32,32,128,1><<<cgrid, 256>>>(ybuf, rw0b, rb0b, cvb, 256);
    instnorm_kernel<<<16*256, 256>>>(cvb, hbuf, out_s3, 32*32, 0);   // h = skip3 + IN(conv)

    // block 1: input = hbuf
    conv_gemm<256,32,32,3,3,1,1,32,32,128,1><<<cgrid, 256>>>(hbuf, rw1a, rb1a, cvb, 256);
    instnorm_kernel<<<16*256, 256>>>(cvb, ybuf, nullptr, 32*32, 1);
    conv_gemm<256,32,32,3,3,1,1,32,32,128,1><<<cgrid, 256>>>(ybuf, rw1b, rb1b, cvb, 256);
    instnorm_kernel<<<16*256, 256>>>(cvb, out_h, hbuf, 32*32, 0);    // final h
}

// round 7
// speedup vs baseline: 1.3234x; 1.1024x over previous
#include <cuda_runtime.h>
#include <math.h>
#include <stdint.h>

// ---------------------------------------------------------------------------
// Scratch (__device__ globals)
// ---------------------------------------------------------------------------
__device__ float g_om1 [16*147*128*128];
__device__ float g_col1[16*147*128*128];
__device__ float g_t1  [16*64*128*128];
__device__ float g_om2 [16*48*64*64];
__device__ float g_col2[16*1024*64*64];
__device__ float g_t2  [16*128*64*64];
__device__ float g_om3 [16*48*32*32];
__device__ float g_col3[16*2048*32*32];
__device__ float g_t3  [16*256*32*32];
__device__ float g_y   [16*256*32*32];
__device__ float g_cv  [16*256*32*32];
__device__ float g_h   [16*256*32*32];

// ---------------------------------------------------------------------------
// bf16 pack/split helpers
// ---------------------------------------------------------------------------
__device__ __forceinline__ uint32_t pack_bf2(float e0, float e1){
    uint32_t r;  // low half = e0, high half = e1
    asm("cvt.rn.bf16x2.f32 %0, %2, %1;" : "=r"(r) : "f"(e0), "f"(e1));
    return r;
}
__device__ __forceinline__ float bf_lo_f(uint32_t p){ return __uint_as_float(p << 16); }
__device__ __forceinline__ float bf_hi_f(uint32_t p){ return __uint_as_float(p & 0xffff0000u); }

// mma.sync m16n8k16 row.col f32 += bf16*bf16 (sm_80+ baseline PTX -> HMMA)
__device__ __forceinline__ void mma_bf16(float* c, const uint32_t* a,
                                         uint32_t b0, uint32_t b1){
    asm volatile(
        "mma.sync.aligned.m16n8k16.row.col.f32.bf16.bf16.f32 "
        "{%0,%1,%2,%3}, {%4,%5,%6,%7}, {%8,%9}, {%0,%1,%2,%3};"
        : "+f"(c[0]), "+f"(c[1]), "+f"(c[2]), "+f"(c[3])
        : "r"(a[0]), "r"(a[1]), "r"(a[2]), "r"(a[3]), "r"(b0), "r"(b1));
}

// ---------------------------------------------------------------------------
// Conv-as-GEMM via mma.sync bf16, hi/lo split (3-pass: hi*hi + hi*lo + lo*hi).
// Tile: 128(M) x 128(N), K chunk 32 fp32. 8 warps: 2(m) x 4(n).
// Smem: k-pair-packed u32 tiles [16][136] per operand per precision level.
// ---------------------------------------------------------------------------
template<int CIN,int H,int W,int KH,int KW,int STR,int PAD,int HO,int WO,int REFLECT,int PASSES>
__global__ void __launch_bounds__(256,1)
conv_mma(const float* __restrict__ in, const float* __restrict__ Wt,
         const float* __restrict__ bias, float* __restrict__ out, int M)
{
    constexpr int Kdim = CIN*KH*KW;
    constexpr int HW   = HO*WO;
    constexpr int BK   = 32;
    constexpr int NT   = (Kdim + BK - 1)/BK;

    __shared__ uint32_t sA[2][16][136];
    __shared__ uint32_t sB[2][16][136];

    const int t   = threadIdx.x;
    const int wid = t >> 5;
    const int lid = t & 31;
    const int gid = lid >> 2;      // 0..7
    const int tid = lid & 3;       // 0..3
    const int wm  = wid & 1;       // m-warp group (x64)
    const int wn  = wid >> 1;      // n-warp group (x32)
    const int mb  = wm*64;
    const int nb  = wn*32;

    const int nTile = blockIdx.x * 128;
    const int mTile = blockIdx.y * 128;

    // ---- B-gather invariants ----
    const int nl  = t & 127;
    const int kq  = t >> 7;        // 0/1
    const int n   = nTile + nl;
    const int b   = n / HW;
    const int rem = n % HW;
    const int oy  = rem / WO;
    const int ox  = rem % WO;
    const int iy0 = oy*STR - PAD;
    const int ix0 = ox*STR - PAD;
    const float* inb = in + (size_t)b*CIN*H*W;

    float fa[16], fb[16];

    auto gatherB = [&](int k) -> float {
        if (k >= Kdim) return 0.f;
        const int ci = k / (KH*KW);
        const int r  = k % (KH*KW);
        const int ky = r / KW;
        const int kx = r % KW;
        int iy = iy0 + ky;
        int ix = ix0 + kx;
        if (REFLECT) {
            iy = iy < 0 ? -iy : (iy >= H ? 2*H-2-iy : iy);
            ix = ix < 0 ? -ix : (ix >= W ? 2*W-2-ix : ix);
            return inb[((size_t)ci*H + iy)*W + ix];
        }
        if (iy >= 0 && iy < H && ix >= 0 && ix < W)
            return inb[((size_t)ci*H + iy)*W + ix];
        return 0.f;
    };
    auto loadA = [&](int k0){
        #pragma unroll
        for (int i = 0; i < 8; i++) {
            const int e  = i*256 + t;
            const int m  = e & 127;
            const int kp = e >> 7;
            const int gm = mTile + m;
            const int k  = k0 + kp*2;
            const bool mv = (gm < M);
            const float* row = Wt + (size_t)gm * (size_t)Kdim;
            fa[2*i]   = (mv && k     < Kdim) ? row[k]   : 0.f;
            fa[2*i+1] = (mv && k + 1 < Kdim) ? row[k+1] : 0.f;
        }
    };
    auto loadB = [&](int k0){
        #pragma unroll
        for (int i = 0; i < 8; i++) {
            const int kp = kq + i*2;
            const int k  = k0 + kp*2;
            fb[2*i]   = gatherB(k);
            fb[2*i+1] = gatherB(k+1);
        }
    };
    auto storeAB = [&](){
        #pragma unroll
        for (int i = 0; i < 8; i++) {
            const int e  = i*256 + t;
            const int m  = e & 127;
            const int kp = e >> 7;
            const uint32_t h = pack_bf2(fa[2*i], fa[2*i+1]);
            sA[0][kp][m] = h;
            if (PASSES > 1)
                sA[1][kp][m] = pack_bf2(fa[2*i]   - bf_lo_f(h),
                                        fa[2*i+1] - bf_hi_f(h));
        }
        #pragma unroll
        for (int i = 0; i < 8; i++) {
            const int kp = kq + i*2;
            const uint32_t h = pack_bf2(fb[2*i], fb[2*i+1]);
            sB[0][kp][nl] = h;
            if (PASSES > 1)
                sB[1][kp][nl] = pack_bf2(fb[2*i]   - bf_lo_f(h),
                                         fb[2*i+1] - bf_hi_f(h));
        }
    };

    float acc[4][4][4];
    #pragma unroll
    for (int mi = 0; mi < 4; mi++)
        #pragma unroll
        for (int ni = 0; ni < 4; ni++)
            #pragma unroll
            for (int c = 0; c < 4; c++) acc[mi][ni][c] = 0.f;

    loadA(0); loadB(0);
    storeAB();
    __syncthreads();

    for (int it = 0; it < NT; it++) {
        const bool more = (it + 1 < NT);
        if (more) { loadA((it+1)*BK); loadB((it+1)*BK); }

        #pragma unroll
        for (int p = 0; p < PASSES; p++) {
            const int pa = (p == 2) ? 1 : 0;
            const int pb = (p == 1) ? 1 : 0;
            #pragma unroll
            for (int ks = 0; ks < 2; ks++) {
                uint32_t af[4][4];
                #pragma unroll
                for (int mi = 0; mi < 4; mi++) {
                    const int m0 = mb + mi*16 + gid;
                    af[mi][0] = sA[pa][ks*8 + tid    ][m0];
                    af[mi][1] = sA[pa][ks*8 + tid    ][m0 + 8];
                    af[mi][2] = sA[pa][ks*8 + tid + 4][m0];
                    af[mi][3] = sA[pa][ks*8 + tid + 4][m0 + 8];
                }
                #pragma unroll
                for (int ni = 0; ni < 4; ni++) {
                    const int n0 = nb + ni*8 + gid;
                    const uint32_t b0 = sB[pb][ks*8 + tid    ][n0];
                    const uint32_t b1 = sB[pb][ks*8 + tid + 4][n0];
                    #pragma unroll
                    for (int mi = 0; mi < 4; mi++)
                        mma_bf16(acc[mi][ni], af[mi], b0, b1);
                }
            }
        }

        __syncthreads();
        if (more) { storeAB(); __syncthreads(); }
    }

    // ---- epilogue: direct register -> gmem (float2 per c-pair) ----
    const int b2   = nTile / HW;
    const int pix0 = nTile % HW;
    #pragma unroll
    for (int mi = 0; mi < 4; mi++) {
        const int r0 = mTile + mb + mi*16 + gid;
        const int r1 = r0 + 8;
        const bool v0 = (r0 < M);
        const bool v1 = (r1 < M);
        const float bv0 = v0 ? bias[r0] : 0.f;
        const float bv1 = v1 ? bias[r1] : 0.f;
        #pragma unroll
        for (int ni = 0; ni < 4; ni++) {
            const int nloc = nb + ni*8 + tid*2;
            if (v0) {
                float2 o0 = make_float2(acc[mi][ni][0] + bv0, acc[mi][ni][1] + bv0);
                *reinterpret_cast<float2*>(out + ((size_t)b2*M + r0)*HW + pix0 + nloc) = o0;
            }
            if (v1) {
                float2 o1 = make_float2(acc[mi][ni][2] + bv1, acc[mi][ni][3] + bv1);
                *reinterpret_cast<float2*>(out + ((size_t)b2*M + r1)*HW + pix0 + nloc) = o1;
            }
        }
    }
}

// ---------------------------------------------------------------------------
// DCNv2 sampling: col[b, ci*K + k, pix] = mask * bilinear(x[b,ci], ys, xs)
// ---------------------------------------------------------------------------
template<int CIN,int H,int W,int KH,int KW,int STR,int PAD,int HO,int WO>
__global__ void __launch_bounds__(256)
deform_sample_kernel(const float* __restrict__ x, const float* __restrict__ om,
                     float* __restrict__ col)
{
    constexpr int B  = 16;
    constexpr int K  = KH*KW;
    constexpr int HW = HO*WO;

    const int idx = blockIdx.x*blockDim.x + threadIdx.x;
    if (idx >= B*K*HW) return;

    const int ox  = idx % WO;
    int tmp       = idx / WO;
    const int oy  = tmp % HO;  tmp /= HO;
    const int k   = tmp % K;
    const int b   = tmp / K;
    const int ky  = k / KW;
    const int kx  = k % KW;

    const int pix = oy*WO + ox;
    const float offy = om[((size_t)(b*3*K + 2*k    )*HW) + pix];
    const float offx = om[((size_t)(b*3*K + 2*k + 1)*HW) + pix];
    const float mv   = om[((size_t)(b*3*K + 2*K + k)*HW) + pix];
    const float mask = 1.f / (1.f + expf(-mv));

    const float ys = (float)(oy*STR - PAD + ky) + offy;
    const float xs = (float)(ox*STR - PAD + kx) + offx;

    const float y0f = floorf(ys), x0f = floorf(xs);
    const float dy = ys - y0f,    dx = xs - x0f;
    const int y0 = (int)y0f, x0 = (int)x0f;
    const int y1 = y0 + 1,   x1 = x0 + 1;

    const bool vy0 = (y0 >= 0) & (y0 < H);
    const bool vy1 = (y1 >= 0) & (y1 < H);
    const bool vx0 = (x0 >= 0) & (x0 < W);
    const bool vx1 = (x1 >= 0) & (x1 < W);

    const int cy0 = min(max(y0, 0), H-1), cy1 = min(max(y1, 0), H-1);
    const int cx0 = min(max(x0, 0), W-1), cx1 = min(max(x1, 0), W-1);

    const float f00 = (vy0 && vx0) ? (1.f-dy)*(1.f-dx)*mask : 0.f;
    const float f01 = (vy0 && vx1) ? (1.f-dy)*dx*mask       : 0.f;
    const float f10 = (vy1 && vx0) ? dy*(1.f-dx)*mask       : 0.f;
    const float f11 = (vy1 && vx1) ? dy*dx*mask             : 0.f;

    const int i00 = cy0*W + cx0, i01 = cy0*W + cx1;
    const int i10 = cy1*W + cx0, i11 = cy1*W + cx1;

    const float* xb = x + (size_t)b*CIN*H*W;
    float* cp = col + (((size_t)b*CIN*K + k)*HW) + pix;

    #pragma unroll 4
    for (int ci = 0; ci < CIN; ci++) {
        const float* img = xb + (size_t)ci*H*W;
        const float v = f00*img[i00] + f01*img[i01] + f10*img[i10] + f11*img[i11];
        cp[(size_t)ci*K*HW] = v;
    }
}

// ---------------------------------------------------------------------------
// Instance norm (two-pass) + optional ReLU + optional residual add.
// ---------------------------------------------------------------------------
__global__ void __launch_bounds__(256)
instnorm_kernel(const float* __restrict__ in, float* __restrict__ out,
                const float* __restrict__ addsrc, int HW, int relu)
{
    const int bc = blockIdx.x;
    const float* p = in + (size_t)bc*HW;
    float* q = out + (size_t)bc*HW;
    const float* a = addsrc ? addsrc + (size_t)bc*HW : nullptr;

    __shared__ float red[256];
    __shared__ float s_mu, s_rs;
    const int t = threadIdx.x;

    float s = 0.f;
    for (int i = t; i < HW; i += 256) s += p[i];
    red[t] = s; __syncthreads();
    for (int o = 128; o > 0; o >>= 1) { if (t < o) red[t] += red[t+o]; __syncthreads(); }
    if (t == 0) s_mu = red[0] / (float)HW;
    __syncthreads();
    const float mu = s_mu;

    float v = 0.f;
    for (int i = t; i < HW; i += 256) { const float d = p[i]-mu; v += d*d; }
    red[t] = v; __syncthreads();
    for (int o = 128; o > 0; o >>= 1) { if (t < o) red[t] += red[t+o]; __syncthreads(); }
    if (t == 0) s_rs = rsqrtf(red[0] / (float)HW + 1e-5f);
    __syncthreads();
    const float rs = s_rs;

    for (int i = t; i < HW; i += 256) {
        float val = (p[i] - mu) * rs;
        if (relu) val = fmaxf(val, 0.f);
        if (a) val += a[i];
        q[i] = val;
    }
}

// ---------------------------------------------------------------------------
// Launch
// ---------------------------------------------------------------------------
extern "C" void kernel_launch(void* const* d_in, const int* in_sizes, int n_in,
                              void* d_out, int out_size)
{
    const float* x      = (const float*)d_in[0];
    const float* w_off1 = (const float*)d_in[1];
    const float* b_off1 = (const float*)d_in[2];
    const float* w1     = (const float*)d_in[3];
    const float* b1     = (const float*)d_in[4];
    const float* w_off2 = (const float*)d_in[5];
    const float* b_off2 = (const float*)d_in[6];
    const float* w2     = (const float*)d_in[7];
    const float* b2     = (const float*)d_in[8];
    const float* w_off3 = (const float*)d_in[9];
    const float* b_off3 = (const float*)d_in[10];
    const float* w3     = (const float*)d_in[11];
    const float* b3     = (const float*)d_in[12];
    const float* rw0a   = (const float*)d_in[13];
    const float* rb0a   = (const float*)d_in[14];
    const float* rw0b   = (const float*)d_in[15];
    const float* rb0b   = (const float*)d_in[16];
    const float* rw1a   = (const float*)d_in[17];
    const float* rb1a   = (const float*)d_in[18];
    const float* rw1b   = (const float*)d_in[19];
    const float* rb1b   = (const float*)d_in[20];

    float* out = (float*)d_out;
    float* out_h  = out;                                   // [16,256,32,32]
    float* out_s2 = out + 16*256*32*32;                    // [16,128,64,64]
    float* out_s3 = out + 16*256*32*32 + 16*128*64*64;     // [16,256,32,32]

    float *om1,*col1,*t1,*om2,*col2,*t2,*om3,*col3,*t3,*ybuf,*cvb,*hbuf;
    cudaGetSymbolAddress((void**)&om1,  g_om1);
    cudaGetSymbolAddress((void**)&col1, g_col1);
    cudaGetSymbolAddress((void**)&t1,   g_t1);
    cudaGetSymbolAddress((void**)&om2,  g_om2);
    cudaGetSymbolAddress((void**)&col2, g_col2);
    cudaGetSymbolAddress((void**)&t2,   g_t2);
    cudaGetSymbolAddress((void**)&om3,  g_om3);
    cudaGetSymbolAddress((void**)&col3, g_col3);
    cudaGetSymbolAddress((void**)&t3,   g_t3);
    cudaGetSymbolAddress((void**)&ybuf, g_y);
    cudaGetSymbolAddress((void**)&cvb,  g_cv);
    cudaGetSymbolAddress((void**)&hbuf, g_h);

    // ------------------ Stage 1: 3 -> 64, 7x7, s1 p3, 128x128 ------------------
    {
        conv_mma<3,128,128,7,7,1,3,128,128,0,3>
            <<<dim3(2048, 2), 256>>>(x, w_off1, b_off1, om1, 147);

        const int tot = 16*49*128*128;
        deform_sample_kernel<3,128,128,7,7,1,3,128,128>
            <<<(tot+255)/256, 256>>>(x, om1, col1);

        conv_mma<147,128,128,1,1,1,0,128,128,0,3>
            <<<dim3(2048, 1), 256>>>(col1, w1, b1, t1, 64);

        instnorm_kernel<<<16*64, 256>>>(t1, t1, nullptr, 128*128, 1);
    }

    // ------------------ Stage 2: 64 -> 128, 4x4, s2 p1, -> 64x64 ---------------
    {
        conv_mma<64,128,128,4,4,2,1,64,64,0,3>
            <<<dim3(512, 1), 256>>>(t1, w_off2, b_off2, om2, 48);

        const int tot = 16*16*64*64;
        deform_sample_kernel<64,128,128,4,4,2,1,64,64>
            <<<(tot+255)/256, 256>>>(t1, om2, col2);

        conv_mma<1024,64,64,1,1,1,0,64,64,0,3>
            <<<dim3(512, 1), 256>>>(col2, w2, b2, t2, 128);

        instnorm_kernel<<<16*128, 256>>>(t2, out_s2, nullptr, 64*64, 1);   // skip2
    }

    // ------------------ Stage 3: 128 -> 256, 4x4, s2 p1, -> 32x32 --------------
    {
        conv_mma<128,64,64,4,4,2,1,32,32,0,3>
            <<<dim3(128, 1), 256>>>(out_s2, w_off3, b_off3, om3, 48);

        const int tot = 16*16*32*32;
        deform_sample_kernel<128,64,64,4,4,2,1,32,32>
            <<<(tot+255)/256, 256>>>(out_s2, om3, col3);

        conv_mma<2048,32,32,1,1,1,0,32,32,0,3>
            <<<dim3(128, 2), 256>>>(col3, w3, b3, t3, 256);

        instnorm_kernel<<<16*256, 256>>>(t3, out_s3, nullptr, 32*32, 1);   // skip3
    }

    // ------------------ Residual blocks on [16,256,32,32] ----------------------
    const dim3 cgrid(128, 2);

    // block 0: input = skip3 (reads d_out region)
    conv_mma<256,32,32,3,3,1,1,32,32,1,3><<<cgrid, 256>>>(out_s3, rw0a, rb0a, cvb, 256);
    instnorm_kernel<<<16*256, 256>>>(cvb, ybuf, nullptr, 32*32, 1);
    conv_mma<256,32,32,3,3,1,1,32,32,1,3><<<cgrid, 256>>>(ybuf, rw0b, rb0b, cvb, 256);
    instnorm_kernel<<<16*256, 256>>>(cvb, hbuf, out_s3, 32*32, 0);   // h = skip3 + IN(conv)

    // block 1: input = hbuf
    conv_mma<256,32,32,3,3,1,1,32,32,1,3><<<cgrid, 256>>>(hbuf, rw1a, rb1a, cvb, 256);
    instnorm_kernel<<<16*256, 256>>>(cvb, ybuf, nullptr, 32*32, 1);
    conv_mma<256,32,32,3,3,1,1,32,32,1,3><<<cgrid, 256>>>(ybuf, rw1b, rb1b, cvb, 256);
    instnorm_kernel<<<16*256, 256>>>(cvb, out_h, hbuf, 32*32, 0);    // final h
}

// round 8
// speedup vs baseline: 1.3888x; 1.0494x over previous
#include <cuda_runtime.h>
#include <math.h>
#include <stdint.h>

// ---------------------------------------------------------------------------
// Scratch (__device__ globals)
// ---------------------------------------------------------------------------
__device__ float g_om1 [16*147*128*128];
__device__ float g_col1[16*147*128*128];
__device__ float g_t1  [16*64*128*128];
__device__ float g_om2 [16*48*64*64];
__device__ float g_col2[16*1024*64*64];
__device__ float g_t2  [16*128*64*64];
__device__ float g_om3 [16*48*32*32];
__device__ float g_col3[16*2048*32*32];
__device__ float g_t3  [16*256*32*32];
__device__ float g_y   [16*256*32*32];
__device__ float g_cv  [16*256*32*32];
__device__ float g_h   [16*256*32*32];

// ---------------------------------------------------------------------------
// bf16 pack/split helpers
// ---------------------------------------------------------------------------
__device__ __forceinline__ uint32_t pack_bf2(float e0, float e1){
    uint32_t r;  // low half = e0, high half = e1
    asm("cvt.rn.bf16x2.f32 %0, %2, %1;" : "=r"(r) : "f"(e0), "f"(e1));
    return r;
}
__device__ __forceinline__ float bf_lo_f(uint32_t p){ return __uint_as_float(p << 16); }
__device__ __forceinline__ float bf_hi_f(uint32_t p){ return __uint_as_float(p & 0xffff0000u); }

// mma.sync m16n8k16 row.col f32 += bf16*bf16 (sm_80+ baseline PTX -> HMMA)
__device__ __forceinline__ void mma_bf16(float* c, const uint32_t* a,
                                         uint32_t b0, uint32_t b1){
    asm volatile(
        "mma.sync.aligned.m16n8k16.row.col.f32.bf16.bf16.f32 "
        "{%0,%1,%2,%3}, {%4,%5,%6,%7}, {%8,%9}, {%0,%1,%2,%3};"
        : "+f"(c[0]), "+f"(c[1]), "+f"(c[2]), "+f"(c[3])
        : "r"(a[0]), "r"(a[1]), "r"(a[2]), "r"(a[3]), "r"(b0), "r"(b1));
}

// ---------------------------------------------------------------------------
// Conv-as-GEMM via mma.sync bf16, hi/lo split (3-pass: hi*hi + hi*lo + lo*hi).
// Tile: BM(M) x 128(N), K chunk 32 fp32. 8 warps: 2(m) x 4(n).
// BM=128 (4 mi/warp, occ 1) or BM=64 (2 mi/warp, occ 2).
// ---------------------------------------------------------------------------
template<int CIN,int H,int W,int KH,int KW,int STR,int PAD,int HO,int WO,int REFLECT,int PASSES,int BM>
__global__ void __launch_bounds__(256, (BM==64) ? 2 : 1)
conv_mma(const float* __restrict__ in, const float* __restrict__ Wt,
         const float* __restrict__ bias, float* __restrict__ out, int M)
{
    constexpr int Kdim = CIN*KH*KW;
    constexpr int HW   = HO*WO;
    constexpr int BK   = 32;
    constexpr int NT   = (Kdim + BK - 1)/BK;
    constexpr int MI   = BM/32;          // mi count per warp
    constexpr int AW   = BM + 8;         // A smem row stride (u32)
    constexpr int AR   = BM/16;          // A elems per thread per load

    __shared__ uint32_t sA[2][16][AW];
    __shared__ uint32_t sB[2][16][136];

    const int t   = threadIdx.x;
    const int wid = t >> 5;
    const int lid = t & 31;
    const int gid = lid >> 2;      // 0..7
    const int tid = lid & 3;       // 0..3
    const int wm  = wid & 1;       // m-warp group
    const int wn  = wid >> 1;      // n-warp group (x32)
    const int mb  = wm*(BM/2);
    const int nb  = wn*32;

    const int nTile = blockIdx.x * 128;
    const int mTile = blockIdx.y * BM;

    // ---- B-gather invariants ----
    const int nl  = t & 127;
    const int kq  = t >> 7;        // 0/1
    const int n   = nTile + nl;
    const int b   = n / HW;
    const int rem = n % HW;
    const int oy  = rem / WO;
    const int ox  = rem % WO;
    const int iy0 = oy*STR - PAD;
    const int ix0 = ox*STR - PAD;
    const float* inb = in + (size_t)b*CIN*H*W;

    float fa[2*AR], fb[16];

    auto gatherB = [&](int k) -> float {
        if (k >= Kdim) return 0.f;
        const int ci = k / (KH*KW);
        const int r  = k % (KH*KW);
        const int ky = r / KW;
        const int kx = r % KW;
        int iy = iy0 + ky;
        int ix = ix0 + kx;
        if (REFLECT) {
            iy = iy < 0 ? -iy : (iy >= H ? 2*H-2-iy : iy);
            ix = ix < 0 ? -ix : (ix >= W ? 2*W-2-ix : ix);
            return inb[((size_t)ci*H + iy)*W + ix];
        }
        if (iy >= 0 && iy < H && ix >= 0 && ix < W)
            return inb[((size_t)ci*H + iy)*W + ix];
        return 0.f;
    };
    auto loadA = [&](int k0){
        #pragma unroll
        for (int i = 0; i < AR; i++) {
            const int e  = i*256 + t;
            const int m  = e % BM;
            const int kp = e / BM;
            const int gm = mTile + m;
            const int k  = k0 + kp*2;
            const bool mv = (gm < M);
            const float* row = Wt + (size_t)gm * (size_t)Kdim;
            fa[2*i]   = (mv && k     < Kdim) ? row[k]   : 0.f;
            fa[2*i+1] = (mv && k + 1 < Kdim) ? row[k+1] : 0.f;
        }
    };
    auto loadB = [&](int k0){
        #pragma unroll
        for (int i = 0; i < 8; i++) {
            const int kp = kq + i*2;
            const int k  = k0 + kp*2;
            fb[2*i]   = gatherB(k);
            fb[2*i+1] = gatherB(k+1);
        }
    };
    auto storeAB = [&](){
        #pragma unroll
        for (int i = 0; i < AR; i++) {
            const int e  = i*256 + t;
            const int m  = e % BM;
            const int kp = e / BM;
            const uint32_t h = pack_bf2(fa[2*i], fa[2*i+1]);
            sA[0][kp][m] = h;
            if (PASSES > 1)
                sA[1][kp][m] = pack_bf2(fa[2*i]   - bf_lo_f(h),
                                        fa[2*i+1] - bf_hi_f(h));
        }
        #pragma unroll
        for (int i = 0; i < 8; i++) {
            const int kp = kq + i*2;
            const uint32_t h = pack_bf2(fb[2*i], fb[2*i+1]);
            sB[0][kp][nl] = h;
            if (PASSES > 1)
                sB[1][kp][nl] = pack_bf2(fb[2*i]   - bf_lo_f(h),
                                         fb[2*i+1] - bf_hi_f(h));
        }
    };

    float acc[MI][4][4];
    #pragma unroll
    for (int mi = 0; mi < MI; mi++)
        #pragma unroll
        for (int ni = 0; ni < 4; ni++)
            #pragma unroll
            for (int c = 0; c < 4; c++) acc[mi][ni][c] = 0.f;

    loadA(0); loadB(0);
    storeAB();
    __syncthreads();

    for (int it = 0; it < NT; it++) {
        const bool more = (it + 1 < NT);
        if (more) { loadA((it+1)*BK); loadB((it+1)*BK); }

        #pragma unroll
        for (int p = 0; p < PASSES; p++) {
            const int pa = (p == 2) ? 1 : 0;
            const int pb = (p == 1) ? 1 : 0;
            #pragma unroll
            for (int ks = 0; ks < 2; ks++) {
                uint32_t af[MI][4];
                #pragma unroll
                for (int mi = 0; mi < MI; mi++) {
                    const int m0 = mb + mi*16 + gid;
                    af[mi][0] = sA[pa][ks*8 + tid    ][m0];
                    af[mi][1] = sA[pa][ks*8 + tid    ][m0 + 8];
                    af[mi][2] = sA[pa][ks*8 + tid + 4][m0];
                    af[mi][3] = sA[pa][ks*8 + tid + 4][m0 + 8];
                }
                #pragma unroll
                for (int ni = 0; ni < 4; ni++) {
                    const int n0 = nb + ni*8 + gid;
                    const uint32_t b0 = sB[pb][ks*8 + tid    ][n0];
                    const uint32_t b1 = sB[pb][ks*8 + tid + 4][n0];
                    #pragma unroll
                    for (int mi = 0; mi < MI; mi++)
                        mma_bf16(acc[mi][ni], af[mi], b0, b1);
                }
            }
        }

        __syncthreads();
        if (more) { storeAB(); __syncthreads(); }
    }

    // ---- epilogue: direct register -> gmem (float2 per c-pair) ----
    const int b2   = nTile / HW;
    const int pix0 = nTile % HW;
    #pragma unroll
    for (int mi = 0; mi < MI; mi++) {
        const int r0 = mTile + mb + mi*16 + gid;
        const int r1 = r0 + 8;
        const bool v0 = (r0 < M);
        const bool v1 = (r1 < M);
        const float bv0 = v0 ? bias[r0] : 0.f;
        const float bv1 = v1 ? bias[r1] : 0.f;
        #pragma unroll
        for (int ni = 0; ni < 4; ni++) {
            const int nloc = nb + ni*8 + tid*2;
            if (v0) {
                float2 o0 = make_float2(acc[mi][ni][0] + bv0, acc[mi][ni][1] + bv0);
                *reinterpret_cast<float2*>(out + ((size_t)b2*M + r0)*HW + pix0 + nloc) = o0;
            }
            if (v1) {
                float2 o1 = make_float2(acc[mi][ni][2] + bv1, acc[mi][ni][3] + bv1);
                *reinterpret_cast<float2*>(out + ((size_t)b2*M + r1)*HW + pix0 + nloc) = o1;
            }
        }
    }
}

// ---------------------------------------------------------------------------
// DCNv2 sampling: col[b, ci*K + k, pix] = mask * bilinear(x[b,ci], ys, xs)
// ---------------------------------------------------------------------------
template<int CIN,int H,int W,int KH,int KW,int STR,int PAD,int HO,int WO>
__global__ void __launch_bounds__(256)
deform_sample_kernel(const float* __restrict__ x, const float* __restrict__ om,
                     float* __restrict__ col)
{
    constexpr int B  = 16;
    constexpr int K  = KH*KW;
    constexpr int HW = HO*WO;

    const int idx = blockIdx.x*blockDim.x + threadIdx.x;
    if (idx >= B*K*HW) return;

    const int ox  = idx % WO;
    int tmp       = idx / WO;
    const int oy  = tmp % HO;  tmp /= HO;
    const int k   = tmp % K;
    const int b   = tmp / K;
    const int ky  = k / KW;
    const int kx  = k % KW;

    const int pix = oy*WO + ox;
    const float offy = om[((size_t)(b*3*K + 2*k    )*HW) + pix];
    const float offx = om[((size_t)(b*3*K + 2*k + 1)*HW) + pix];
    const float mv   = om[((size_t)(b*3*K + 2*K + k)*HW) + pix];
    const float mask = 1.f / (1.f + expf(-mv));

    const float ys = (float)(oy*STR - PAD + ky) + offy;
    const float xs = (float)(ox*STR - PAD + kx) + offx;

    const float y0f = floorf(ys), x0f = floorf(xs);
    const float dy = ys - y0f,    dx = xs - x0f;
    const int y0 = (int)y0f, x0 = (int)x0f;
    const int y1 = y0 + 1,   x1 = x0 + 1;

    const bool vy0 = (y0 >= 0) & (y0 < H);
    const bool vy1 = (y1 >= 0) & (y1 < H);
    const bool vx0 = (x0 >= 0) & (x0 < W);
    const bool vx1 = (x1 >= 0) & (x1 < W);

    const int cy0 = min(max(y0, 0), H-1), cy1 = min(max(y1, 0), H-1);
    const int cx0 = min(max(x0, 0), W-1), cx1 = min(max(x1, 0), W-1);

    const float f00 = (vy0 && vx0) ? (1.f-dy)*(1.f-dx)*mask : 0.f;
    const float f01 = (vy0 && vx1) ? (1.f-dy)*dx*mask       : 0.f;
    const float f10 = (vy1 && vx0) ? dy*(1.f-dx)*mask       : 0.f;
    const float f11 = (vy1 && vx1) ? dy*dx*mask             : 0.f;

    const int i00 = cy0*W + cx0, i01 = cy0*W + cx1;
    const int i10 = cy1*W + cx0, i11 = cy1*W + cx1;

    const float* xb = x + (size_t)b*CIN*H*W;
    float* cp = col + (((size_t)b*CIN*K + k)*HW) + pix;

    #pragma unroll 4
    for (int ci = 0; ci < CIN; ci++) {
        const float* img = xb + (size_t)ci*H*W;
        const float v = f00*img[i00] + f01*img[i01] + f10*img[i10] + f11*img[i11];
        cp[(size_t)ci*K*HW] = v;
    }
}

// ---------------------------------------------------------------------------
// Instance norm (two-pass) + optional ReLU + optional residual add.
// ---------------------------------------------------------------------------
__global__ void __launch_bounds__(256)
instnorm_kernel(const float* __restrict__ in, float* __restrict__ out,
                const float* __restrict__ addsrc, int HW, int relu)
{
    const int bc = blockIdx.x;
    const float* p = in + (size_t)bc*HW;
    float* q = out + (size_t)bc*HW;
    const float* a = addsrc ? addsrc + (size_t)bc*HW : nullptr;

    __shared__ float red[256];
    __shared__ float s_mu, s_rs;
    const int t = threadIdx.x;

    float s = 0.f;
    for (int i = t; i < HW; i += 256) s += p[i];
    red[t] = s; __syncthreads();
    for (int o = 128; o > 0; o >>= 1) { if (t < o) red[t] += red[t+o]; __syncthreads(); }
    if (t == 0) s_mu = red[0] / (float)HW;
    __syncthreads();
    const float mu = s_mu;

    float v = 0.f;
    for (int i = t; i < HW; i += 256) { const float d = p[i]-mu; v += d*d; }
    red[t] = v; __syncthreads();
    for (int o = 128; o > 0; o >>= 1) { if (t < o) red[t] += red[t+o]; __syncthreads(); }
    if (t == 0) s_rs = rsqrtf(red[0] / (float)HW + 1e-5f);
    __syncthreads();
    const float rs = s_rs;

    for (int i = t; i < HW; i += 256) {
        float val = (p[i] - mu) * rs;
        if (relu) val = fmaxf(val, 0.f);
        if (a) val += a[i];
        q[i] = val;
    }
}

// ---------------------------------------------------------------------------
// Launch
// ---------------------------------------------------------------------------
extern "C" void kernel_launch(void* const* d_in, const int* in_sizes, int n_in,
                              void* d_out, int out_size)
{
    const float* x      = (const float*)d_in[0];
    const float* w_off1 = (const float*)d_in[1];
    const float* b_off1 = (const float*)d_in[2];
    const float* w1     = (const float*)d_in[3];
    const float* b1     = (const float*)d_in[4];
    const float* w_off2 = (const float*)d_in[5];
    const float* b_off2 = (const float*)d_in[6];
    const float* w2     = (const float*)d_in[7];
    const float* b2     = (const float*)d_in[8];
    const float* w_off3 = (const float*)d_in[9];
    const float* b_off3 = (const float*)d_in[10];
    const float* w3     = (const float*)d_in[11];
    const float* b3     = (const float*)d_in[12];
    const float* rw0a   = (const float*)d_in[13];
    const float* rb0a   = (const float*)d_in[14];
    const float* rw0b   = (const float*)d_in[15];
    const float* rb0b   = (const float*)d_in[16];
    const float* rw1a   = (const float*)d_in[17];
    const float* rb1a   = (const float*)d_in[18];
    const float* rw1b   = (const float*)d_in[19];
    const float* rb1b   = (const float*)d_in[20];

    float* out = (float*)d_out;
    float* out_h  = out;                                   // [16,256,32,32]
    float* out_s2 = out + 16*256*32*32;                    // [16,128,64,64]
    float* out_s3 = out + 16*256*32*32 + 16*128*64*64;     // [16,256,32,32]

    float *om1,*col1,*t1,*om2,*col2,*t2,*om3,*col3,*t3,*ybuf,*cvb,*hbuf;
    cudaGetSymbolAddress((void**)&om1,  g_om1);
    cudaGetSymbolAddress((void**)&col1, g_col1);
    cudaGetSymbolAddress((void**)&t1,   g_t1);
    cudaGetSymbolAddress((void**)&om2,  g_om2);
    cudaGetSymbolAddress((void**)&col2, g_col2);
    cudaGetSymbolAddress((void**)&t2,   g_t2);
    cudaGetSymbolAddress((void**)&om3,  g_om3);
    cudaGetSymbolAddress((void**)&col3, g_col3);
    cudaGetSymbolAddress((void**)&t3,   g_t3);
    cudaGetSymbolAddress((void**)&ybuf, g_y);
    cudaGetSymbolAddress((void**)&cvb,  g_cv);
    cudaGetSymbolAddress((void**)&hbuf, g_h);

    // ------------------ Stage 1: 3 -> 64, 7x7, s1 p3, 128x128 ------------------
    {
        conv_mma<3,128,128,7,7,1,3,128,128,0,3,64>
            <<<dim3(2048, 3), 256>>>(x, w_off1, b_off1, om1, 147);

        const int tot = 16*49*128*128;
        deform_sample_kernel<3,128,128,7,7,1,3,128,128>
            <<<(tot+255)/256, 256>>>(x, om1, col1);

        conv_mma<147,128,128,1,1,1,0,128,128,0,3,64>
            <<<dim3(2048, 1), 256>>>(col1, w1, b1, t1, 64);

        instnorm_kernel<<<16*64, 256>>>(t1, t1, nullptr, 128*128, 1);
    }

    // ------------------ Stage 2: 64 -> 128, 4x4, s2 p1, -> 64x64 ---------------
    {
        conv_mma<64,128,128,4,4,2,1,64,64,0,3,64>
            <<<dim3(512, 1), 256>>>(t1, w_off2, b_off2, om2, 48);

        const int tot = 16*16*64*64;
        deform_sample_kernel<64,128,128,4,4,2,1,64,64>
            <<<(tot+255)/256, 256>>>(t1, om2, col2);

        conv_mma<1024,64,64,1,1,1,0,64,64,0,3,128>
            <<<dim3(512, 1), 256>>>(col2, w2, b2, t2, 128);

        instnorm_kernel<<<16*128, 256>>>(t2, out_s2, nullptr, 64*64, 1);   // skip2
    }

    // ------------------ Stage 3: 128 -> 256, 4x4, s2 p1, -> 32x32 --------------
    {
        conv_mma<128,64,64,4,4,2,1,32,32,0,3,64>
            <<<dim3(128, 1), 256>>>(out_s2, w_off3, b_off3, om3, 48);

        const int tot = 16*16*32*32;
        deform_sample_kernel<128,64,64,4,4,2,1,32,32>
            <<<(tot+255)/256, 256>>>(out_s2, om3, col3);

        conv_mma<2048,32,32,1,1,1,0,32,32,0,3,128>
            <<<dim3(128, 2), 256>>>(col3, w3, b3, t3, 256);

        instnorm_kernel<<<16*256, 256>>>(t3, out_s3, nullptr, 32*32, 1);   // skip3
    }

    // ------------------ Residual blocks on [16,256,32,32] ----------------------
    const dim3 cgrid(128, 2);

    // block 0: input = skip3 (reads d_out region)
    conv_mma<256,32,32,3,3,1,1,32,32,1,3,128><<<cgrid, 256>>>(out_s3, rw0a, rb0a, cvb, 256);
    instnorm_kernel<<<16*256, 256>>>(cvb, ybuf, nullptr, 32*32, 1);
    conv_mma<256,32,32,3,3,1,1,32,32,1,3,128><<<cgrid, 256>>>(ybuf, rw0b, rb0b, cvb, 256);
    instnorm_kernel<<<16*256, 256>>>(cvb, hbuf, out_s3, 32*32, 0);   // h = skip3 + IN(conv)

    // block 1: input = hbuf
    conv_mma<256,32,32,3,3,1,1,32,32,1,3,128><<<cgrid, 256>>>(hbuf, rw1a, rb1a, cvb, 256);
    instnorm_kernel<<<16*256, 256>>>(cvb, ybuf, nullptr, 32*32, 1);
    conv_mma<256,32,32,3,3,1,1,32,32,1,3,128><<<cgrid, 256>>>(ybuf, rw1b, rb1b, cvb, 256);
    instnorm_kernel<<<16*256, 256>>>(cvb, out_h, hbuf, 32*32, 0);    // final h
}

// round 9
// speedup vs baseline: 2.0358x; 1.4658x over previous
#include <cuda_runtime.h>
#include <math.h>
#include <stdint.h>

// ---------------------------------------------------------------------------
// Scratch (__device__ globals)
// ---------------------------------------------------------------------------
__device__ float g_om1 [16*147*128*128];
__device__ float g_col1[16*147*128*128];
__device__ float g_t1  [16*64*128*128];
__device__ float g_om2 [16*48*64*64];
__device__ float g_col2[16*1024*64*64];
__device__ float g_t2  [16*128*64*64];
__device__ float g_om3 [16*48*32*32];
__device__ float g_col3[16*2048*32*32];
__device__ float g_t3  [16*256*32*32];
__device__ float g_y   [16*256*32*32];
__device__ float g_cv  [16*256*32*32];
__device__ float g_h   [16*256*32*32];

// ---------------------------------------------------------------------------
// bf16 pack/split helpers
// ---------------------------------------------------------------------------
__device__ __forceinline__ uint32_t pack_bf2(float e0, float e1){
    uint32_t r;  // low half = e0, high half = e1
    asm("cvt.rn.bf16x2.f32 %0, %2, %1;" : "=r"(r) : "f"(e0), "f"(e1));
    return r;
}
__device__ __forceinline__ float bf_lo_f(uint32_t p){ return __uint_as_float(p << 16); }
__device__ __forceinline__ float bf_hi_f(uint32_t p){ return __uint_as_float(p & 0xffff0000u); }

// mma.sync m16n8k16 row.col f32 += bf16*bf16 (sm_80+ baseline PTX -> HMMA)
__device__ __forceinline__ void mma_bf16(float* c, const uint32_t* a,
                                         uint32_t b0, uint32_t b1){
    asm volatile(
        "mma.sync.aligned.m16n8k16.row.col.f32.bf16.bf16.f32 "
        "{%0,%1,%2,%3}, {%4,%5,%6,%7}, {%8,%9}, {%0,%1,%2,%3};"
        : "+f"(c[0]), "+f"(c[1]), "+f"(c[2]), "+f"(c[3])
        : "r"(a[0]), "r"(a[1]), "r"(a[2]), "r"(a[3]), "r"(b0), "r"(b1));
}

// ---------------------------------------------------------------------------
// Conv-as-GEMM via mma.sync bf16, hi/lo split, 3 passes (hi*hi + hi*lo + lo*hi).
// Tile BM(M) x 128(N), K chunk 32 fp32. 8 warps: 2(m) x 4(n).
// Fragment-native smem layout: A frags read via LDS.128, B via LDS.64,
// conflict-free both sides; frag sets loaded once per ks, reused over passes.
// ---------------------------------------------------------------------------
template<int CIN,int H,int W,int KH,int KW,int STR,int PAD,int HO,int WO,int REFLECT,int BM>
__global__ void __launch_bounds__(256, (BM==64) ? 2 : 1)
conv_mma(const float* __restrict__ in, const float* __restrict__ Wt,
         const float* __restrict__ bias, float* __restrict__ out, int M)
{
    constexpr int Kdim = CIN*KH*KW;
    constexpr int HW   = HO*WO;
    constexpr int BK   = 32;
    constexpr int NT   = (Kdim + BK - 1)/BK;
    constexpr int MI   = BM/32;            // mi count per warp
    constexpr int SAV  = MI*4 + 4;         // A per-lane stride (u32): odd mult of 16B
    constexpr int AR   = BM/16;            // A producer iters
    constexpr int EMASK= 4*MI - 1;
    constexpr int ESH  = (MI==4) ? 4 : 3;  // log2(4*MI)
    constexpr int A_U32= 512*SAV;          // [2buf][2pa][2ks][2wm][32][SAV]

    extern __shared__ __align__(16) uint32_t sm[];
    uint32_t* sBm = sm + A_U32;            // [2buf][2pb][2ks][4wn][32][10]

    const int t    = threadIdx.x;
    const int lane = t & 31;
    const int w8   = t >> 5;
    const int gidl = lane >> 2;
    const int tidl = lane & 3;
    const int g4   = lane >> 3;            // A store bank-shift group
    const int g2   = lane >> 4;            // B store bank-shift group

    const int wid = w8;
    const int wm  = wid & 1;
    const int wn  = wid >> 1;
    const int mb  = wm*(BM/2);
    const int nb  = wn*32;

    const int nTile = blockIdx.x * 128;
    const int mTile = blockIdx.y * BM;

    auto aOff = [&](int buf,int pa,int ks,int wmi,int ln,int e)->int{
        return ((((buf*2+pa)*2+ks)*2+wmi)*32 + ln)*SAV + e;
    };
    auto bOff = [&](int buf,int pb,int ks,int wni,int ln,int e)->int{
        return ((((buf*2+pb)*2+ks)*4+wni)*32 + ln)*10 + e;
    };

    auto gatherB = [&](int n, int k)->float{
        if (k >= Kdim) return 0.f;
        const int b   = n / HW;
        const int rem = n % HW;
        const int oy  = rem / WO;
        const int ox  = rem % WO;
        const int ci  = k / (KH*KW);
        const int r   = k % (KH*KW);
        const int ky  = r / KW;
        const int kx  = r % KW;
        int iy = oy*STR - PAD + ky;
        int ix = ox*STR - PAD + kx;
        const float* inb = in + (size_t)b*CIN*H*W;
        if (REFLECT) {
            iy = iy < 0 ? -iy : (iy >= H ? 2*H-2-iy : iy);
            ix = ix < 0 ? -ix : (ix >= W ? 2*W-2-ix : ix);
            return inb[((size_t)ci*H + iy)*W + ix];
        }
        if (iy >= 0 && iy < H && ix >= 0 && ix < W)
            return inb[((size_t)ci*H + iy)*W + ix];
        return 0.f;
    };

    float fa[2*AR], fb[16];

    auto loadA = [&](int k0){
        #pragma unroll
        for (int i = 0; i < AR; i++) {
            const int v   = i*8 + w8;
            const int elt = (v + g4) & EMASK;
            const int wm_ = (v >> ESH) & 1;
            const int ks_ = v >> (ESH+1); (void)ks_;
            const int mi_ = elt >> 2;
            const int j   = elt & 3;
            const int m   = wm_*(BM/2) + mi_*16 + (j & 1)*8 + gidl;
            const int kp  = (v >> (ESH+1))*8 + (j >> 1)*4 + tidl;
            const int gm  = mTile + m;
            const int k   = k0 + kp*2;
            const bool mv = (gm < M);
            const float* row = Wt + (size_t)gm * (size_t)Kdim;
            fa[2*i]   = (mv && k     < Kdim) ? row[k]   : 0.f;
            fa[2*i+1] = (mv && k + 1 < Kdim) ? row[k+1] : 0.f;
        }
    };
    auto loadB = [&](int k0){
        #pragma unroll
        for (int i = 0; i < 8; i++) {
            const int v   = i*8 + w8;
            const int ni2 = ((v & 7) + g2) & 7;
            const int wn_ = (v >> 3) & 3;
            const int ks_ = v >> 5;
            const int n   = nTile + wn_*32 + (ni2 >> 1)*8 + gidl;
            const int kp  = ks_*8 + (ni2 & 1)*4 + tidl;
            const int k   = k0 + kp*2;
            fb[2*i]   = gatherB(n, k);
            fb[2*i+1] = gatherB(n, k+1);
        }
    };
    auto storeAB = [&](int buf){
        #pragma unroll
        for (int i = 0; i < AR; i++) {
            const int v   = i*8 + w8;
            const int elt = (v + g4) & EMASK;
            const int wm_ = (v >> ESH) & 1;
            const int ks_ = v >> (ESH+1);
            const uint32_t h = pack_bf2(fa[2*i], fa[2*i+1]);
            const uint32_t l = pack_bf2(fa[2*i]   - bf_lo_f(h),
                                        fa[2*i+1] - bf_hi_f(h));
            sm[aOff(buf,0,ks_,wm_,lane,elt)] = h;
            sm[aOff(buf,1,ks_,wm_,lane,elt)] = l;
        }
        #pragma unroll
        for (int i = 0; i < 8; i++) {
            const int v   = i*8 + w8;
            const int ni2 = ((v & 7) + g2) & 7;
            const int wn_ = (v >> 3) & 3;
            const int ks_ = v >> 5;
            const uint32_t h = pack_bf2(fb[2*i], fb[2*i+1]);
            const uint32_t l = pack_bf2(fb[2*i]   - bf_lo_f(h),
                                        fb[2*i+1] - bf_hi_f(h));
            sBm[bOff(buf,0,ks_,wn_,lane,ni2)] = h;
            sBm[bOff(buf,1,ks_,wn_,lane,ni2)] = l;
        }
    };

    float acc[MI][4][4];
    #pragma unroll
    for (int mi = 0; mi < MI; mi++)
        #pragma unroll
        for (int ni = 0; ni < 4; ni++)
            #pragma unroll
            for (int c = 0; c < 4; c++) acc[mi][ni][c] = 0.f;

    loadA(0); loadB(0);
    storeAB(0);
    __syncthreads();

    for (int it = 0; it < NT; it++) {
        const int cur  = it & 1;
        const bool more = (it + 1 < NT);
        if (more) { loadA((it+1)*BK); loadB((it+1)*BK); }

        #pragma unroll
        for (int ks = 0; ks < 2; ks++) {
            uint4 afv[2][MI];
            #pragma unroll
            for (int pa = 0; pa < 2; pa++)
                #pragma unroll
                for (int mi = 0; mi < MI; mi++)
                    afv[pa][mi] = *reinterpret_cast<const uint4*>(
                        &sm[aOff(cur,pa,ks,wm,lane,mi*4)]);
            uint2 bvv[2][4];
            #pragma unroll
            for (int pb = 0; pb < 2; pb++)
                #pragma unroll
                for (int ni = 0; ni < 4; ni++)
                    bvv[pb][ni] = *reinterpret_cast<const uint2*>(
                        &sBm[bOff(cur,pb,ks,wn,lane,ni*2)]);

            #pragma unroll
            for (int p = 0; p < 3; p++) {
                const int pa = (p == 2) ? 1 : 0;
                const int pb = (p == 1) ? 1 : 0;
                #pragma unroll
                for (int ni = 0; ni < 4; ni++)
                    #pragma unroll
                    for (int mi = 0; mi < MI; mi++)
                        mma_bf16(acc[mi][ni],
                                 reinterpret_cast<const uint32_t*>(&afv[pa][mi]),
                                 bvv[pb][ni].x, bvv[pb][ni].y);
            }
        }

        if (more) {
            storeAB(cur ^ 1);
            __syncthreads();
        }
    }

    // ---- epilogue: direct register -> gmem (float2 per c-pair) ----
    const int b2   = nTile / HW;
    const int pix0 = nTile % HW;
    #pragma unroll
    for (int mi = 0; mi < MI; mi++) {
        const int r0 = mTile + mb + mi*16 + gidl;
        const int r1 = r0 + 8;
        const bool v0 = (r0 < M);
        const bool v1 = (r1 < M);
        const float bv0 = v0 ? bias[r0] : 0.f;
        const float bv1 = v1 ? bias[r1] : 0.f;
        #pragma unroll
        for (int ni = 0; ni < 4; ni++) {
            const int nloc = nb + ni*8 + tidl*2;
            if (v0) {
                float2 o0 = make_float2(acc[mi][ni][0] + bv0, acc[mi][ni][1] + bv0);
                *reinterpret_cast<float2*>(out + ((size_t)b2*M + r0)*HW + pix0 + nloc) = o0;
            }
            if (v1) {
                float2 o1 = make_float2(acc[mi][ni][2] + bv1, acc[mi][ni][3] + bv1);
                *reinterpret_cast<float2*>(out + ((size_t)b2*M + r1)*HW + pix0 + nloc) = o1;
            }
        }
    }
}

// smem byte sizes per BM
static constexpr int smemBytes(int BM){
    const int SAV = BM/8 + 4;
    return (512*SAV + 10240) * 4;
}

// ---------------------------------------------------------------------------
// DCNv2 sampling: col[b, ci*K + k, pix] = mask * bilinear(x[b,ci], ys, xs)
// ---------------------------------------------------------------------------
template<int CIN,int H,int W,int KH,int KW,int STR,int PAD,int HO,int WO>
__global__ void __launch_bounds__(256)
deform_sample_kernel(const float* __restrict__ x, const float* __restrict__ om,
                     float* __restrict__ col)
{
    constexpr int B  = 16;
    constexpr int K  = KH*KW;
    constexpr int HW = HO*WO;

    const int idx = blockIdx.x*blockDim.x + threadIdx.x;
    if (idx >= B*K*HW) return;

    const int ox  = idx % WO;
    int tmp       = idx / WO;
    const int oy  = tmp % HO;  tmp /= HO;
    const int k   = tmp % K;
    const int b   = tmp / K;
    const int ky  = k / KW;
    const int kx  = k % KW;

    const int pix = oy*WO + ox;
    const float offy = om[((size_t)(b*3*K + 2*k    )*HW) + pix];
    const float offx = om[((size_t)(b*3*K + 2*k + 1)*HW) + pix];
    const float mv   = om[((size_t)(b*3*K + 2*K + k)*HW) + pix];
    const float mask = 1.f / (1.f + expf(-mv));

    const float ys = (float)(oy*STR - PAD + ky) + offy;
    const float xs = (float)(ox*STR - PAD + kx) + offx;

    const float y0f = floorf(ys), x0f = floorf(xs);
    const float dy = ys - y0f,    dx = xs - x0f;
    const int y0 = (int)y0f, x0 = (int)x0f;
    const int y1 = y0 + 1,   x1 = x0 + 1;

    const bool vy0 = (y0 >= 0) & (y0 < H);
    const bool vy1 = (y1 >= 0) & (y1 < H);
    const bool vx0 = (x0 >= 0) & (x0 < W);
    const bool vx1 = (x1 >= 0) & (x1 < W);

    const int cy0 = min(max(y0, 0), H-1), cy1 = min(max(y1, 0), H-1);
    const int cx0 = min(max(x0, 0), W-1), cx1 = min(max(x1, 0), W-1);

    const float f00 = (vy0 && vx0) ? (1.f-dy)*(1.f-dx)*mask : 0.f;
    const float f01 = (vy0 && vx1) ? (1.f-dy)*dx*mask       : 0.f;
    const float f10 = (vy1 && vx0) ? dy*(1.f-dx)*mask       : 0.f;
    const float f11 = (vy1 && vx1) ? dy*dx*mask             : 0.f;

    const int i00 = cy0*W + cx0, i01 = cy0*W + cx1;
    const int i10 = cy1*W + cx0, i11 = cy1*W + cx1;

    const float* xb = x + (size_t)b*CIN*H*W;
    float* cp = col + (((size_t)b*CIN*K + k)*HW) + pix;

    #pragma unroll 4
    for (int ci = 0; ci < CIN; ci++) {
        const float* img = xb + (size_t)ci*H*W;
        const float v = f00*img[i00] + f01*img[i01] + f10*img[i10] + f11*img[i11];
        cp[(size_t)ci*K*HW] = v;
    }
}

// ---------------------------------------------------------------------------
// Instance norm (two-pass) + optional ReLU + optional residual add.
// ---------------------------------------------------------------------------
__global__ void __launch_bounds__(256)
instnorm_kernel(const float* __restrict__ in, float* __restrict__ out,
                const float* __restrict__ addsrc, int HW, int relu)
{
    const int bc = blockIdx.x;
    const float* p = in + (size_t)bc*HW;
    float* q = out + (size_t)bc*HW;
    const float* a = addsrc ? addsrc + (size_t)bc*HW : nullptr;

    __shared__ float red[256];
    __shared__ float s_mu, s_rs;
    const int t = threadIdx.x;

    float s = 0.f;
    for (int i = t; i < HW; i += 256) s += p[i];
    red[t] = s; __syncthreads();
    for (int o = 128; o > 0; o >>= 1) { if (t < o) red[t] += red[t+o]; __syncthreads(); }
    if (t == 0) s_mu = red[0] / (float)HW;
    __syncthreads();
    const float mu = s_mu;

    float v = 0.f;
    for (int i = t; i < HW; i += 256) { const float d = p[i]-mu; v += d*d; }
    red[t] = v; __syncthreads();
    for (int o = 128; o > 0; o >>= 1) { if (t < o) red[t] += red[t+o]; __syncthreads(); }
    if (t == 0) s_rs = rsqrtf(red[0] / (float)HW + 1e-5f);
    __syncthreads();
    const float rs = s_rs;

    for (int i = t; i < HW; i += 256) {
        float val = (p[i] - mu) * rs;
        if (relu) val = fmaxf(val, 0.f);
        if (a) val += a[i];
        q[i] = val;
    }
}

// ---------------------------------------------------------------------------
// Launch
// ---------------------------------------------------------------------------
extern "C" void kernel_launch(void* const* d_in, const int* in_sizes, int n_in,
                              void* d_out, int out_size)
{
    const float* x      = (const float*)d_in[0];
    const float* w_off1 = (const float*)d_in[1];
    const float* b_off1 = (const float*)d_in[2];
    const float* w1     = (const float*)d_in[3];
    const float* b1     = (const float*)d_in[4];
    const float* w_off2 = (const float*)d_in[5];
    const float* b_off2 = (const float*)d_in[6];
    const float* w2     = (const float*)d_in[7];
    const float* b2     = (const float*)d_in[8];
    const float* w_off3 = (const float*)d_in[9];
    const float* b_off3 = (const float*)d_in[10];
    const float* w3     = (const float*)d_in[11];
    const float* b3     = (const float*)d_in[12];
    const float* rw0a   = (const float*)d_in[13];
    const float* rb0a   = (const float*)d_in[14];
    const float* rw0b   = (const float*)d_in[15];
    const float* rb0b   = (const float*)d_in[16];
    const float* rw1a   = (const float*)d_in[17];
    const float* rb1a   = (const float*)d_in[18];
    const float* rw1b   = (const float*)d_in[19];
    const float* rb1b   = (const float*)d_in[20];

    float* out = (float*)d_out;
    float* out_h  = out;                                   // [16,256,32,32]
    float* out_s2 = out + 16*256*32*32;                    // [16,128,64,64]
    float* out_s3 = out + 16*256*32*32 + 16*128*64*64;     // [16,256,32,32]

    float *om1,*col1,*t1,*om2,*col2,*t2,*om3,*col3,*t3,*ybuf,*cvb,*hbuf;
    cudaGetSymbolAddress((void**)&om1,  g_om1);
    cudaGetSymbolAddress((void**)&col1, g_col1);
    cudaGetSymbolAddress((void**)&t1,   g_t1);
    cudaGetSymbolAddress((void**)&om2,  g_om2);
    cudaGetSymbolAddress((void**)&col2, g_col2);
    cudaGetSymbolAddress((void**)&t2,   g_t2);
    cudaGetSymbolAddress((void**)&om3,  g_om3);
    cudaGetSymbolAddress((void**)&col3, g_col3);
    cudaGetSymbolAddress((void**)&t3,   g_t3);
    cudaGetSymbolAddress((void**)&ybuf, g_y);
    cudaGetSymbolAddress((void**)&cvb,  g_cv);
    cudaGetSymbolAddress((void**)&hbuf, g_h);

    constexpr int S64  = smemBytes(64);    // 65536
    constexpr int S128 = smemBytes(128);   // 81920

    auto setmax = [](const void* f, int bytes){
        cudaFuncSetAttribute(f, cudaFuncAttributeMaxDynamicSharedMemorySize, bytes);
    };
    setmax((const void*)conv_mma<3,128,128,7,7,1,3,128,128,0,64>,     S64);
    setmax((const void*)conv_mma<147,128,128,1,1,1,0,128,128,0,64>,   S64);
    setmax((const void*)conv_mma<64,128,128,4,4,2,1,64,64,0,64>,      S64);
    setmax((const void*)conv_mma<1024,64,64,1,1,1,0,64,64,0,128>,     S128);
    setmax((const void*)conv_mma<128,64,64,4,4,2,1,32,32,0,64>,       S64);
    setmax((const void*)conv_mma<2048,32,32,1,1,1,0,32,32,0,128>,     S128);
    setmax((const void*)conv_mma<256,32,32,3,3,1,1,32,32,1,128>,      S128);

    // ------------------ Stage 1: 3 -> 64, 7x7, s1 p3, 128x128 ------------------
    {
        conv_mma<3,128,128,7,7,1,3,128,128,0,64>
            <<<dim3(2048, 3), 256, S64>>>(x, w_off1, b_off1, om1, 147);

        const int tot = 16*49*128*128;
        deform_sample_kernel<3,128,128,7,7,1,3,128,128>
            <<<(tot+255)/256, 256>>>(x, om1, col1);

        conv_mma<147,128,128,1,1,1,0,128,128,0,64>
            <<<dim3(2048, 1), 256, S64>>>(col1, w1, b1, t1, 64);

        instnorm_kernel<<<16*64, 256>>>(t1, t1, nullptr, 128*128, 1);
    }

    // ------------------ Stage 2: 64 -> 128, 4x4, s2 p1, -> 64x64 ---------------
    {
        conv_mma<64,128,128,4,4,2,1,64,64,0,64>
            <<<dim3(512, 1), 256, S64>>>(t1, w_off2, b_off2, om2, 48);

        const int tot = 16*16*64*64;
        deform_sample_kernel<64,128,128,4,4,2,1,64,64>
            <<<(tot+255)/256, 256>>>(t1, om2, col2);

        conv_mma<1024,64,64,1,1,1,0,64,64,0,128>
            <<<dim3(512, 1), 256, S128>>>(col2, w2, b2, t2, 128);

        instnorm_kernel<<<16*128, 256>>>(t2, out_s2, nullptr, 64*64, 1);   // skip2
    }

    // ------------------ Stage 3: 128 -> 256, 4x4, s2 p1, -> 32x32 --------------
    {
        conv_mma<128,64,64,4,4,2,1,32,32,0,64>
            <<<dim3(128, 1), 256, S64>>>(out_s2, w_off3, b_off3, om3, 48);

        const int tot = 16*16*32*32;
        deform_sample_kernel<128,64,64,4,4,2,1,32,32>
            <<<(tot+255)/256, 256>>>(out_s2, om3, col3);

        conv_mma<2048,32,32,1,1,1,0,32,32,0,128>
            <<<dim3(128, 2), 256, S128>>>(col3, w3, b3, t3, 256);

        instnorm_kernel<<<16*256, 256>>>(t3, out_s3, nullptr, 32*32, 1);   // skip3
    }

    // ------------------ Residual blocks on [16,256,32,32] ----------------------
    const dim3 cgrid(128, 2);

    // block 0: input = skip3 (reads d_out region)
    conv_mma<256,32,32,3,3,1,1,32,32,1,128><<<cgrid, 256, S128>>>(out_s3, rw0a, rb0a, cvb, 256);
    instnorm_kernel<<<16*256, 256>>>(cvb, ybuf, nullptr, 32*32, 1);
    conv_mma<256,32,32,3,3,1,1,32,32,1,128><<<cgrid, 256, S128>>>(ybuf, rw0b, rb0b, cvb, 256);
    instnorm_kernel<<<16*256, 256>>>(cvb, hbuf, out_s3, 32*32, 0);   // h = skip3 + IN(conv)

    // block 1: input = hbuf
    conv_mma<256,32,32,3,3,1,1,32,32,1,128><<<cgrid, 256, S128>>>(hbuf, rw1a, rb1a, cvb, 256);
    instnorm_kernel<<<16*256, 256>>>(cvb, ybuf, nullptr, 32*32, 1);
    conv_mma<256,32,32,3,3,1,1,32,32,1,128><<<cgrid, 256, S128>>>(ybuf, rw1b, rb1b, cvb, 256);
    instnorm_kernel<<<16*256, 256>>>(cvb, out_h, hbuf, 32*32, 0);    // final h
}